// round 1
// baseline (speedup 1.0000x reference)
#include <cuda_runtime.h>
#include <math.h>

#define HQ   32
#define DDIM 128
#define QLEN 2048
#define BM   64
#define BN   64
#define NTHREADS 256

// smem layout (floats):
//  sQ : [64][128]      ->  8192 floats  (float4 [64][32])
//  sK : [64][132]      ->  8448 floats  (float4 [64][33], padded row => conflict-free)
//  sV : [64][128]      ->  8192 floats  (float4 [64][32])
//  sP : [64][65]       ->  4160 floats
#define SK_OFF 8192
#define SV_OFF 16640
#define SP_OFF 24832
#define SMEM_FLOATS 28992
#define SMEM_BYTES (SMEM_FLOATS * 4)

__global__ void __launch_bounds__(NTHREADS, 1)
roco_attn_kernel(const float* __restrict__ Qg, const float* __restrict__ Kg,
                 const float* __restrict__ Vg, float* __restrict__ Outg,
                 float* __restrict__ roco, float* __restrict__ roco_sq)
{
    extern __shared__ float smem[];
    float4* sQ4 = reinterpret_cast<float4*>(smem);
    float4* sK4 = reinterpret_cast<float4*>(smem + SK_OFF);
    float4* sV4 = reinterpret_cast<float4*>(smem + SV_OFF);
    float*  sP  = smem + SP_OFF;

    const int h  = blockIdx.y;
    const int qt = (gridDim.x - 1) - blockIdx.x;   // heavy tiles first
    const int q0 = qt * BM;
    const int tid = threadIdx.x;
    const int w   = tid >> 5;
    const int l   = tid & 31;
    const float scale = 0.08838834764831845f;      // 1/sqrt(128)

    const float4* gq = reinterpret_cast<const float4*>(Qg);
    const float4* gk = reinterpret_cast<const float4*>(Kg);
    const float4* gv = reinterpret_cast<const float4*>(Vg);

    // ---- load Q tile (kept resident for both passes) ----
    for (int i = tid; i < BM * 32; i += NTHREADS) {
        int m = i >> 5, d4 = i & 31;
        sQ4[m * 32 + d4] = gq[((size_t)(q0 + m) * HQ + h) * 32 + d4];
    }

    const int m0 = w * 8;
    float rmax[8], rsum[8];
#pragma unroll
    for (int r = 0; r < 8; r++) { rmax[r] = -1e30f; rsum[r] = 0.0f; }

    // =================== PASS 1: row max + row sum ===================
    for (int kt = 0; kt <= qt; ++kt) {
        const int k0 = kt * BN;
        __syncthreads();
        for (int i = tid; i < BN * 32; i += NTHREADS) {
            int n = i >> 5, d4 = i & 31;
            sK4[n * 33 + d4] = gk[((size_t)(k0 + n) * HQ + h) * 32 + d4];
        }
        __syncthreads();

        float acc0[8], acc1[8];
#pragma unroll
        for (int r = 0; r < 8; r++) { acc0[r] = 0.0f; acc1[r] = 0.0f; }

#pragma unroll 4
        for (int d4 = 0; d4 < 32; ++d4) {
            float4 kv0 = sK4[l * 33 + d4];
            float4 kv1 = sK4[(l + 32) * 33 + d4];
#pragma unroll
            for (int r = 0; r < 8; r++) {
                float4 qv = sQ4[(m0 + r) * 32 + d4];
                acc0[r] = fmaf(qv.x, kv0.x, acc0[r]);
                acc0[r] = fmaf(qv.y, kv0.y, acc0[r]);
                acc0[r] = fmaf(qv.z, kv0.z, acc0[r]);
                acc0[r] = fmaf(qv.w, kv0.w, acc0[r]);
                acc1[r] = fmaf(qv.x, kv1.x, acc1[r]);
                acc1[r] = fmaf(qv.y, kv1.y, acc1[r]);
                acc1[r] = fmaf(qv.z, kv1.z, acc1[r]);
                acc1[r] = fmaf(qv.w, kv1.w, acc1[r]);
            }
        }

#pragma unroll
        for (int r = 0; r < 8; r++) {
            const int ig = q0 + m0 + r;
            float s0 = (k0 + l      <= ig) ? acc0[r] * scale : -1e30f;
            float s1 = (k0 + l + 32 <= ig) ? acc1[r] * scale : -1e30f;
            float tm = fmaxf(s0, s1);
#pragma unroll
            for (int off = 16; off > 0; off >>= 1)
                tm = fmaxf(tm, __shfl_xor_sync(0xffffffffu, tm, off));
            float mnew = fmaxf(rmax[r], tm);
            float e = __expf(s0 - mnew) + __expf(s1 - mnew);
#pragma unroll
            for (int off = 16; off > 0; off >>= 1)
                e += __shfl_xor_sync(0xffffffffu, e, off);
            rsum[r] = rsum[r] * __expf(rmax[r] - mnew) + e;
            rmax[r] = mnew;
        }
    }

    float invl[8];
#pragma unroll
    for (int r = 0; r < 8; r++) invl[r] = 1.0f / rsum[r];

    float4 oacc[8];
#pragma unroll
    for (int r = 0; r < 8; r++) oacc[r] = make_float4(0.f, 0.f, 0.f, 0.f);

    // =================== PASS 2: P, O, roco ===================
    for (int kt = 0; kt <= qt; ++kt) {
        const int k0 = kt * BN;
        __syncthreads();
        for (int i = tid; i < BN * 32; i += NTHREADS) {
            int n = i >> 5, d4 = i & 31;
            sK4[n * 33 + d4] = gk[((size_t)(k0 + n) * HQ + h) * 32 + d4];
            sV4[n * 32 + d4] = gv[((size_t)(k0 + n) * HQ + h) * 32 + d4];
        }
        __syncthreads();

        float acc0[8], acc1[8];
#pragma unroll
        for (int r = 0; r < 8; r++) { acc0[r] = 0.0f; acc1[r] = 0.0f; }

#pragma unroll 4
        for (int d4 = 0; d4 < 32; ++d4) {
            float4 kv0 = sK4[l * 33 + d4];
            float4 kv1 = sK4[(l + 32) * 33 + d4];
#pragma unroll
            for (int r = 0; r < 8; r++) {
                float4 qv = sQ4[(m0 + r) * 32 + d4];
                acc0[r] = fmaf(qv.x, kv0.x, acc0[r]);
                acc0[r] = fmaf(qv.y, kv0.y, acc0[r]);
                acc0[r] = fmaf(qv.z, kv0.z, acc0[r]);
                acc0[r] = fmaf(qv.w, kv0.w, acc0[r]);
                acc1[r] = fmaf(qv.x, kv1.x, acc1[r]);
                acc1[r] = fmaf(qv.y, kv1.y, acc1[r]);
                acc1[r] = fmaf(qv.z, kv1.z, acc1[r]);
                acc1[r] = fmaf(qv.w, kv1.w, acc1[r]);
            }
        }

        float cs0 = 0.f, cs1 = 0.f, cq0 = 0.f, cq1 = 0.f;
#pragma unroll
        for (int r = 0; r < 8; r++) {
            const int ig = q0 + m0 + r;
            float p0 = (k0 + l      <= ig) ? __expf(acc0[r] * scale - rmax[r]) * invl[r] : 0.0f;
            float p1 = (k0 + l + 32 <= ig) ? __expf(acc1[r] * scale - rmax[r]) * invl[r] : 0.0f;
            sP[(m0 + r) * 65 + l]      = p0;
            sP[(m0 + r) * 65 + l + 32] = p1;
            cs0 += p0; cq0 = fmaf(p0, p0, cq0);
            cs1 += p1; cq1 = fmaf(p1, p1, cq1);
        }
        atomicAdd(&roco[h * QLEN + k0 + l],         cs0);
        atomicAdd(&roco[h * QLEN + k0 + l + 32],    cs1);
        atomicAdd(&roco_sq[h * QLEN + k0 + l],      cq0);
        atomicAdd(&roco_sq[h * QLEN + k0 + l + 32], cq1);

        // P rows [m0, m0+8) were written by this warp itself; sV covered by the
        // earlier __syncthreads(). PV directly:
#pragma unroll 4
        for (int n = 0; n < BN; ++n) {
            float4 vv = sV4[n * 32 + l];
#pragma unroll
            for (int r = 0; r < 8; r++) {
                float pr = sP[(m0 + r) * 65 + n];
                oacc[r].x = fmaf(pr, vv.x, oacc[r].x);
                oacc[r].y = fmaf(pr, vv.y, oacc[r].y);
                oacc[r].z = fmaf(pr, vv.z, oacc[r].z);
                oacc[r].w = fmaf(pr, vv.w, oacc[r].w);
            }
        }
    }

    // ---- write O: lane owns d = 4l..4l+3 ----
    float4* gout = reinterpret_cast<float4*>(Outg);
#pragma unroll
    for (int r = 0; r < 8; r++)
        gout[((size_t)(q0 + m0 + r) * HQ + h) * 32 + l] = oacc[r];
}

__global__ void zero_kernel(float* __restrict__ p, int n)
{
    int i = blockIdx.x * blockDim.x + threadIdx.x;
    if (i < n) p[i] = 0.0f;
}

extern "C" void kernel_launch(void* const* d_in, const int* in_sizes, int n_in,
                              void* d_out, int out_size)
{
    const float* Qg = (const float*)d_in[0];
    const float* Kg = (const float*)d_in[1];
    const float* Vg = (const float*)d_in[2];
    float* Outg    = (float*)d_out;
    float* roco    = Outg + (size_t)QLEN * HQ * DDIM;   // 8388608
    float* roco_sq = roco + HQ * QLEN;                  // +65536

    cudaFuncSetAttribute(roco_attn_kernel,
                         cudaFuncAttributeMaxDynamicSharedMemorySize, SMEM_BYTES);

    const int nz = 2 * HQ * QLEN;   // 131072
    zero_kernel<<<(nz + 255) / 256, 256>>>(roco, nz);

    dim3 grid(QLEN / BM, HQ);       // (32, 32)
    roco_attn_kernel<<<grid, NTHREADS, SMEM_BYTES>>>(Qg, Kg, Vg, Outg, roco, roco_sq);
}

// round 2
// speedup vs baseline: 1.1111x; 1.1111x over previous
#include <cuda_runtime.h>
#include <math.h>

#define HQ   32
#define DDIM 128
#define QLEN 2048
#define BM   64
#define BN   64
#define NTHREADS 256

typedef unsigned long long u64;

// ---- smem layout (float offsets) ----
//  sQ : [64][128]                 = 8192
//  sK : [2][64][132]  (33 f4 pitch, conflict-free) = 2*8448 = 16896
//  sV : [2][64][128]              = 2*8192 = 16384
//  sP : [64][68]      (16B-aligned rows)           = 4352
#define SQ_OFF 0
#define SK_OFF 8192
#define SK_BUF 8448
#define SV_OFF 25088
#define SV_BUF 8192
#define SP_OFF 41472
#define SMEM_FLOATS 45824
#define SMEM_BYTES (SMEM_FLOATS * 4)

#define FMA2(acc, a, b) asm("fma.rn.f32x2 %0, %1, %2, %0;" : "+l"(acc) : "l"(a), "l"(b))
#define PACK2(d, f)     asm("mov.b64 %0, {%1, %1};" : "=l"(d) : "f"(f))
#define UNPACK2(lo, hi, d) asm("mov.b64 {%0, %1}, %2;" : "=f"(lo), "=f"(hi) : "l"(d))
#define LDS128_2U64(lo, hi, addr) \
    asm("ld.shared.v2.b64 {%0, %1}, [%2];" : "=l"(lo), "=l"(hi) : "r"(addr))
#define LDS128_F4(a, b, c, d, addr) \
    asm("ld.shared.v4.f32 {%0, %1, %2, %3}, [%4];" : "=f"(a), "=f"(b), "=f"(c), "=f"(d) : "r"(addr))
#define CPA16(dst, src) \
    asm volatile("cp.async.cg.shared.global [%0], [%1], 16;" :: "r"(dst), "l"(src))
#define CPC() asm volatile("cp.async.commit_group;" ::: "memory")
template<int N> __device__ __forceinline__ void cp_wait() {
    asm volatile("cp.async.wait_group %0;" :: "n"(N) : "memory");
}

__global__ void __launch_bounds__(NTHREADS, 1)
roco_attn_kernel(const float* __restrict__ Qg, const float* __restrict__ Kg,
                 const float* __restrict__ Vg, float* __restrict__ Outg,
                 float* __restrict__ roco, float* __restrict__ roco_sq)
{
    extern __shared__ float smem[];
    const unsigned sb  = (unsigned)__cvta_generic_to_shared(smem);
    const unsigned sQb = sb + SQ_OFF * 4;
    const unsigned sKb = sb + SK_OFF * 4;
    const unsigned sVb = sb + SV_OFF * 4;
    const unsigned sPb = sb + SP_OFF * 4;
    float* sP = smem + SP_OFF;

    const int h  = blockIdx.y;
    const int qt = (gridDim.x - 1) - blockIdx.x;   // heavy tiles first
    const int q0 = qt * BM;
    const int tid = threadIdx.x;
    const int w   = tid >> 5;
    const int l   = tid & 31;
    const float scale = 0.08838834764831845f;      // 1/sqrt(128)

    const float4* gq = reinterpret_cast<const float4*>(Qg);
    const float4* gk = reinterpret_cast<const float4*>(Kg);
    const float4* gv = reinterpret_cast<const float4*>(Vg);

    float4* sQ4 = reinterpret_cast<float4*>(smem);

    // ---- load Q tile (resident for both passes) ----
    for (int i = tid; i < BM * 32; i += NTHREADS) {
        int m = i >> 5, d4 = i & 31;
        sQ4[m * 32 + d4] = gq[((size_t)(q0 + m) * HQ + h) * 32 + d4];
    }

    const int m0 = w * 8;
    float rmax[8], rsum[8];
#pragma unroll
    for (int r = 0; r < 8; r++) { rmax[r] = -1e30f; rsum[r] = 0.0f; }

    // =================== PASS 1: row max + row sum ===================
    {
        // prologue: prefetch tile 0
#pragma unroll
        for (int i = tid; i < BN * 32; i += NTHREADS) {
            int n = i >> 5, d4 = i & 31;
            CPA16(sKb + (n * 132 + d4 * 4) * 4,
                  &gk[((size_t)n * HQ + h) * 32 + d4]);
        }
        CPC();

        for (int kt = 0; kt <= qt; ++kt) {
            const int cur = kt & 1;
            __syncthreads();   // protect buffer (cur^1) being overwritten below
            if (kt < qt) {
                const int k1 = (kt + 1) * BN;
#pragma unroll
                for (int i = tid; i < BN * 32; i += NTHREADS) {
                    int n = i >> 5, d4 = i & 31;
                    CPA16(sKb + ((cur ^ 1) * SK_BUF + n * 132 + d4 * 4) * 4,
                          &gk[((size_t)(k1 + n) * HQ + h) * 32 + d4]);
                }
                CPC();
                cp_wait<1>();
            } else {
                cp_wait<0>();
            }
            __syncthreads();   // current buffer visible to all

            const int k0 = kt * BN;
            u64 acc[8][2];
#pragma unroll
            for (int r = 0; r < 8; r++) { acc[r][0] = 0ull; acc[r][1] = 0ull; }

            const unsigned kRow0 = sKb + (cur * SK_BUF + l * 132) * 4;
            const unsigned kRow1 = sKb + (cur * SK_BUF + (l + 32) * 132) * 4;
            const unsigned qRow  = sQb + (m0 * 128) * 4;

#pragma unroll 4
            for (int d4 = 0; d4 < 32; ++d4) {
                u64 ka0, ka1, kb0, kb1;
                LDS128_2U64(ka0, ka1, kRow0 + d4 * 16);
                LDS128_2U64(kb0, kb1, kRow1 + d4 * 16);
#pragma unroll
                for (int r = 0; r < 8; r++) {
                    u64 q0v, q1v;
                    LDS128_2U64(q0v, q1v, qRow + (r * 128) * 4 + d4 * 16);
                    FMA2(acc[r][0], q0v, ka0);
                    FMA2(acc[r][0], q1v, ka1);
                    FMA2(acc[r][1], q0v, kb0);
                    FMA2(acc[r][1], q1v, kb1);
                }
            }

#pragma unroll
            for (int r = 0; r < 8; r++) {
                const int ig = q0 + m0 + r;
                float lo, hi, s0, s1;
                UNPACK2(lo, hi, acc[r][0]);
                s0 = (k0 + l      <= ig) ? (lo + hi) * scale : -1e30f;
                UNPACK2(lo, hi, acc[r][1]);
                s1 = (k0 + l + 32 <= ig) ? (lo + hi) * scale : -1e30f;
                float tm = fmaxf(s0, s1);
#pragma unroll
                for (int off = 16; off > 0; off >>= 1)
                    tm = fmaxf(tm, __shfl_xor_sync(0xffffffffu, tm, off));
                float mnew = fmaxf(rmax[r], tm);
                float e = __expf(s0 - mnew) + __expf(s1 - mnew);
#pragma unroll
                for (int off = 16; off > 0; off >>= 1)
                    e += __shfl_xor_sync(0xffffffffu, e, off);
                rsum[r] = rsum[r] * __expf(rmax[r] - mnew) + e;
                rmax[r] = mnew;
            }
        }
    }

    float invl[8];
#pragma unroll
    for (int r = 0; r < 8; r++) invl[r] = 1.0f / rsum[r];

    u64 o2[8][2];
#pragma unroll
    for (int r = 0; r < 8; r++) { o2[r][0] = 0ull; o2[r][1] = 0ull; }

    // =================== PASS 2: P, O, roco ===================
    {
        __syncthreads();   // pass-1 compute on K buf0 done before overwrite
#pragma unroll
        for (int i = tid; i < BN * 32; i += NTHREADS) {
            int n = i >> 5, d4 = i & 31;
            CPA16(sKb + (n * 132 + d4 * 4) * 4, &gk[((size_t)n * HQ + h) * 32 + d4]);
            CPA16(sVb + (n * 128 + d4 * 4) * 4, &gv[((size_t)n * HQ + h) * 32 + d4]);
        }
        CPC();

        for (int kt = 0; kt <= qt; ++kt) {
            const int cur = kt & 1;
            __syncthreads();
            if (kt < qt) {
                const int k1 = (kt + 1) * BN;
#pragma unroll
                for (int i = tid; i < BN * 32; i += NTHREADS) {
                    int n = i >> 5, d4 = i & 31;
                    CPA16(sKb + ((cur ^ 1) * SK_BUF + n * 132 + d4 * 4) * 4,
                          &gk[((size_t)(k1 + n) * HQ + h) * 32 + d4]);
                    CPA16(sVb + ((cur ^ 1) * SV_BUF + n * 128 + d4 * 4) * 4,
                          &gv[((size_t)(k1 + n) * HQ + h) * 32 + d4]);
                }
                CPC();
                cp_wait<1>();
            } else {
                cp_wait<0>();
            }
            __syncthreads();

            const int k0 = kt * BN;
            u64 acc[8][2];
#pragma unroll
            for (int r = 0; r < 8; r++) { acc[r][0] = 0ull; acc[r][1] = 0ull; }

            const unsigned kRow0 = sKb + (cur * SK_BUF + l * 132) * 4;
            const unsigned kRow1 = sKb + (cur * SK_BUF + (l + 32) * 132) * 4;
            const unsigned qRow  = sQb + (m0 * 128) * 4;

#pragma unroll 4
            for (int d4 = 0; d4 < 32; ++d4) {
                u64 ka0, ka1, kb0, kb1;
                LDS128_2U64(ka0, ka1, kRow0 + d4 * 16);
                LDS128_2U64(kb0, kb1, kRow1 + d4 * 16);
#pragma unroll
                for (int r = 0; r < 8; r++) {
                    u64 q0v, q1v;
                    LDS128_2U64(q0v, q1v, qRow + (r * 128) * 4 + d4 * 16);
                    FMA2(acc[r][0], q0v, ka0);
                    FMA2(acc[r][0], q1v, ka1);
                    FMA2(acc[r][1], q0v, kb0);
                    FMA2(acc[r][1], q1v, kb1);
                }
            }

            float cs0 = 0.f, cs1 = 0.f, cq0 = 0.f, cq1 = 0.f;
#pragma unroll
            for (int r = 0; r < 8; r++) {
                const int ig = q0 + m0 + r;
                float lo, hi;
                UNPACK2(lo, hi, acc[r][0]);
                float p0 = (k0 + l      <= ig) ? __expf((lo + hi) * scale - rmax[r]) * invl[r] : 0.0f;
                UNPACK2(lo, hi, acc[r][1]);
                float p1 = (k0 + l + 32 <= ig) ? __expf((lo + hi) * scale - rmax[r]) * invl[r] : 0.0f;
                sP[(m0 + r) * 68 + l]      = p0;
                sP[(m0 + r) * 68 + l + 32] = p1;
                cs0 += p0; cq0 = fmaf(p0, p0, cq0);
                cs1 += p1; cq1 = fmaf(p1, p1, cq1);
            }
            atomicAdd(&roco[h * QLEN + k0 + l],         cs0);
            atomicAdd(&roco[h * QLEN + k0 + l + 32],    cs1);
            atomicAdd(&roco_sq[h * QLEN + k0 + l],      cq0);
            atomicAdd(&roco_sq[h * QLEN + k0 + l + 32], cq1);
            __syncwarp();   // lanes read whole rows of sP written by sibling lanes

            // PV: lane owns d = 4l..4l+3 (two f32x2 pairs)
            const unsigned vBase = sVb + (cur * SV_BUF) * 4 + l * 16;
            const unsigned pBase = sPb + (m0 * 68) * 4;
#pragma unroll 2
            for (int n4 = 0; n4 < 16; ++n4) {
                u64 v0a, v0b, v1a, v1b, v2a, v2b, v3a, v3b;
                LDS128_2U64(v0a, v0b, vBase + ((n4 * 4 + 0) * 128) * 4);
                LDS128_2U64(v1a, v1b, vBase + ((n4 * 4 + 1) * 128) * 4);
                LDS128_2U64(v2a, v2b, vBase + ((n4 * 4 + 2) * 128) * 4);
                LDS128_2U64(v3a, v3b, vBase + ((n4 * 4 + 3) * 128) * 4);
#pragma unroll
                for (int r = 0; r < 8; r++) {
                    float pa, pb, pc, pd;
                    LDS128_F4(pa, pb, pc, pd, pBase + (r * 68 + n4 * 4) * 4);
                    u64 p2;
                    PACK2(p2, pa); FMA2(o2[r][0], p2, v0a); FMA2(o2[r][1], p2, v0b);
                    PACK2(p2, pb); FMA2(o2[r][0], p2, v1a); FMA2(o2[r][1], p2, v1b);
                    PACK2(p2, pc); FMA2(o2[r][0], p2, v2a); FMA2(o2[r][1], p2, v2b);
                    PACK2(p2, pd); FMA2(o2[r][0], p2, v3a); FMA2(o2[r][1], p2, v3b);
                }
            }
        }
    }

    // ---- write O: lane owns d = 4l..4l+3 ----
    float4* gout = reinterpret_cast<float4*>(Outg);
#pragma unroll
    for (int r = 0; r < 8; r++) {
        float4 o;
        UNPACK2(o.x, o.y, o2[r][0]);
        UNPACK2(o.z, o.w, o2[r][1]);
        gout[((size_t)(q0 + m0 + r) * HQ + h) * 32 + l] = o;
    }
}

__global__ void zero_kernel(float* __restrict__ p, int n)
{
    int i = blockIdx.x * blockDim.x + threadIdx.x;
    if (i < n) p[i] = 0.0f;
}

extern "C" void kernel_launch(void* const* d_in, const int* in_sizes, int n_in,
                              void* d_out, int out_size)
{
    const float* Qg = (const float*)d_in[0];
    const float* Kg = (const float*)d_in[1];
    const float* Vg = (const float*)d_in[2];
    float* Outg    = (float*)d_out;
    float* roco    = Outg + (size_t)QLEN * HQ * DDIM;   // 8388608
    float* roco_sq = roco + HQ * QLEN;                  // +65536

    cudaFuncSetAttribute(roco_attn_kernel,
                         cudaFuncAttributeMaxDynamicSharedMemorySize, SMEM_BYTES);

    const int nz = 2 * HQ * QLEN;   // 131072
    zero_kernel<<<(nz + 255) / 256, 256>>>(roco, nz);

    dim3 grid(QLEN / BM, HQ);       // (32, 32)
    roco_attn_kernel<<<grid, NTHREADS, SMEM_BYTES>>>(Qg, Kg, Vg, Outg, roco, roco_sq);
}

// round 4
// speedup vs baseline: 1.1401x; 1.0261x over previous
#include <cuda_runtime.h>
#include <math.h>

#define HQ   32
#define QLEN 2048
#define DDIM 128
#define BM   64
#define BN   64
#define NT   256

typedef unsigned long long u64;

// 512MB unnormalized exp(S) scratch + 256KB invl  (device globals = sanctioned scratch)
__device__ float E_scratch[(long long)HQ * QLEN * QLEN];
__device__ float invl_g[HQ * QLEN];

// ---- smem layout (float offsets), all rows padded to 132 floats ----
#define SQ_OFF  0          // [64][132]
#define SK_OFF  8448       // 2 x [64][132]
#define SK_BUF  8448
#define SV_OFF  25344      // 2 x [64][132]
#define SV_BUF  8448
#define SE_OFF  42240      // [64][132]  duplicated-pair E tile
#define RED_OFF 50688      // [4][64] rsum partials
#define INV_OFF 50944      // [64] invl
#define SMEM_FLOATS 51008
#define SMEM_BYTES (SMEM_FLOATS * 4)

#define FMA2(acc, a, b) asm("fma.rn.f32x2 %0, %1, %2, %0;" : "+l"(acc) : "l"(a), "l"(b))
#define PACK2(d, f)     asm("mov.b64 %0, {%1, %1};" : "=l"(d) : "f"(f))
#define UNPACK2(lo, hi, d) asm("mov.b64 {%0, %1}, %2;" : "=f"(lo), "=f"(hi) : "l"(d))
#define LDS128_2U64(lo, hi, addr) \
    asm("ld.shared.v2.b64 {%0, %1}, [%2];" : "=l"(lo), "=l"(hi) : "r"(addr))
#define STS128_2U64(addr, lo, hi) \
    asm volatile("st.shared.v2.b64 [%0], {%1, %2};" :: "r"(addr), "l"(lo), "l"(hi))
#define CPA16(dst, src) \
    asm volatile("cp.async.cg.shared.global [%0], [%1], 16;" :: "r"(dst), "l"(src))
#define CPC() asm volatile("cp.async.commit_group;" ::: "memory")
template<int N> __device__ __forceinline__ void cp_wait() {
    asm volatile("cp.async.wait_group %0;" :: "n"(N) : "memory");
}

__global__ void __launch_bounds__(NT, 1)
roco_fused_kernel(const float* __restrict__ Qg, const float* __restrict__ Kg,
                  const float* __restrict__ Vg, float* __restrict__ Outg)
{
    extern __shared__ float smem[];
    const unsigned sb  = (unsigned)__cvta_generic_to_shared(smem);
    const unsigned sQb = sb + SQ_OFF * 4;
    const unsigned sKb = sb + SK_OFF * 4;
    const unsigned sVb = sb + SV_OFF * 4;
    const unsigned sEb = sb + SE_OFF * 4;
    float* redb  = smem + RED_OFF;
    float* invls = smem + INV_OFF;

    const int h  = blockIdx.y;
    const int qt = (gridDim.x - 1) - blockIdx.x;   // heavy tiles first
    const int q0 = qt * BM;
    const int tid = threadIdx.x;
    const int w   = tid >> 5;
    const int l   = tid & 31;
    const float scale = 0.08838834764831845f;      // 1/sqrt(128)

    // QK mapping: warp (wm,wn) tile 32m x 16n; lane (li,lj) owns 4m x 4n
    const int wm = w >> 2, wn = w & 3;
    const int li = l >> 2, lj = l & 3;
    const int mBase = wm * 32 + li * 4;            // + r (0..3)
    const int nBase = wn * 16 + lj * 4;            // + c (0..3)

    // PV mapping: warp w owns d-cols [w*16, w*16+16); lane (mg,dg): rows s*8+mg, d = w*16+dg*4
    const int mg = l >> 2, dg = l & 3;
    const int dOff = w * 16 + dg * 4;

    const float4* gq = reinterpret_cast<const float4*>(Qg);
    const float4* gk = reinterpret_cast<const float4*>(Kg);
    const float4* gv = reinterpret_cast<const float4*>(Vg);

    // ---- load Q tile (padded rows of 132 floats) ----
    float4* sQ4 = reinterpret_cast<float4*>(smem);
    for (int i = tid; i < BM * 32; i += NT) {
        int m = i >> 5, d4 = i & 31;
        sQ4[m * 33 + d4] = gq[((size_t)(q0 + m) * HQ + h) * 32 + d4];
    }

    // ---- prologue: prefetch K,V tile 0 ----
    for (int i = tid; i < BN * 32; i += NT) {
        int n = i >> 5, d4 = i & 31;
        CPA16(sKb + (n * 132 + d4 * 4) * 4, &gk[((size_t)n * HQ + h) * 32 + d4]);
        CPA16(sVb + (n * 132 + d4 * 4) * 4, &gv[((size_t)n * HQ + h) * 32 + d4]);
    }
    CPC();

    float rpart[4];
#pragma unroll
    for (int r = 0; r < 4; r++) rpart[r] = 0.0f;
    u64 o2[8][2];
#pragma unroll
    for (int s = 0; s < 8; s++) { o2[s][0] = 0ull; o2[s][1] = 0ull; }

    for (int kt = 0; kt <= qt; ++kt) {
        const int cur = kt & 1;
        const int k0 = kt * BN;
        __syncthreads();                           // (a) prev PV done
        if (kt < qt) {
            const int k1 = (kt + 1) * BN;
            for (int i = tid; i < BN * 32; i += NT) {
                int n = i >> 5, d4 = i & 31;
                CPA16(sKb + ((cur ^ 1) * SK_BUF + n * 132 + d4 * 4) * 4,
                      &gk[((size_t)(k1 + n) * HQ + h) * 32 + d4]);
                CPA16(sVb + ((cur ^ 1) * SV_BUF + n * 132 + d4 * 4) * 4,
                      &gv[((size_t)(k1 + n) * HQ + h) * 32 + d4]);
            }
            CPC();
            cp_wait<1>();
        } else {
            cp_wait<0>();
        }
        __syncthreads();                           // (b) cur K,V visible

        // ================= QK^T =================
        u64 acc2[4][4];
#pragma unroll
        for (int r = 0; r < 4; r++)
#pragma unroll
            for (int c = 0; c < 4; c++) acc2[r][c] = 0ull;

        const unsigned qA = sQb + (mBase * 132) * 4;
        const unsigned kA = sKb + (cur * SK_BUF + nBase * 132) * 4;

#pragma unroll 2
        for (int d4 = 0; d4 < 32; ++d4) {
            u64 qa[4][2], kb[4][2];
#pragma unroll
            for (int r = 0; r < 4; r++)
                LDS128_2U64(qa[r][0], qa[r][1], qA + (r * 132 + d4 * 4) * 4);
#pragma unroll
            for (int c = 0; c < 4; c++)
                LDS128_2U64(kb[c][0], kb[c][1], kA + (c * 132 + d4 * 4) * 4);
#pragma unroll
            for (int r = 0; r < 4; r++)
#pragma unroll
                for (int c = 0; c < 4; c++) {
                    FMA2(acc2[r][c], qa[r][0], kb[c][0]);
                    FMA2(acc2[r][c], qa[r][1], kb[c][1]);
                }
        }

        // ============ epilogue: exp, E store, dup STS, rsum ============
#pragma unroll
        for (int r = 0; r < 4; r++) {
            const int qrow = q0 + mBase + r;
            float ev[4];
#pragma unroll
            for (int c = 0; c < 4; c++) {
                float lo, hi;
                UNPACK2(lo, hi, acc2[r][c]);
                float s = (lo + hi) * scale;
                ev[c] = (k0 + nBase + c <= qrow) ? __expf(s) : 0.0f;
            }
            rpart[r] += (ev[0] + ev[1]) + (ev[2] + ev[3]);
            // global E store
            *reinterpret_cast<float4*>(
                &E_scratch[((long long)(h * QLEN + qrow)) * QLEN + k0 + nBase]) =
                make_float4(ev[0], ev[1], ev[2], ev[3]);
            // duplicated-pair smem store: sE[m][2k]=sE[m][2k+1]=e[k]
            u64 p0, p1, p2, p3;
            PACK2(p0, ev[0]); PACK2(p1, ev[1]); PACK2(p2, ev[2]); PACK2(p3, ev[3]);
            const unsigned eA = sEb + ((mBase + r) * 132 + wn * 32 + lj * 8) * 4;
            STS128_2U64(eA, p0, p1);
            STS128_2U64(eA + 16, p2, p3);
        }
        __syncthreads();                           // (c) sE visible

        // ================= PV (d-split, unnormalized) =================
        const unsigned vA = sVb + (cur * SV_BUF) * 4 + dOff * 4;
        const unsigned eA = sEb + mg * 132 * 4;
#pragma unroll 2
        for (int j = 0; j < 32; ++j) {             // n pair {2j, 2j+1}
            u64 v0a, v0b, v1a, v1b;
            LDS128_2U64(v0a, v0b, vA + ((2 * j) * 132) * 4);
            LDS128_2U64(v1a, v1b, vA + ((2 * j + 1) * 132) * 4);
#pragma unroll
            for (int s = 0; s < 8; s++) {
                u64 e0, e1;
                LDS128_2U64(e0, e1, eA + (s * 8 * 132 + 4 * j) * 4);
                FMA2(o2[s][0], e0, v0a); FMA2(o2[s][1], e0, v0b);
                FMA2(o2[s][0], e1, v1a); FMA2(o2[s][1], e1, v1b);
            }
        }
    }

    // ---- rsum reduction, invl, O scale+store ----
#pragma unroll
    for (int r = 0; r < 4; r++) {
        rpart[r] += __shfl_xor_sync(0xffffffffu, rpart[r], 1);
        rpart[r] += __shfl_xor_sync(0xffffffffu, rpart[r], 2);
    }
    if (lj == 0) {
#pragma unroll
        for (int r = 0; r < 4; r++) redb[wn * 64 + mBase + r] = rpart[r];
    }
    __syncthreads();
    if (tid < 64) {
        float s = redb[tid] + redb[64 + tid] + redb[128 + tid] + redb[192 + tid];
        float iv = 1.0f / s;
        invls[tid] = iv;
        invl_g[h * QLEN + q0 + tid] = iv;
    }
    __syncthreads();

    float4* gout = reinterpret_cast<float4*>(Outg);
#pragma unroll
    for (int s = 0; s < 8; s++) {
        const int row = s * 8 + mg;
        const float iv = invls[row];
        float4 o;
        UNPACK2(o.x, o.y, o2[s][0]);
        UNPACK2(o.z, o.w, o2[s][1]);
        o.x *= iv; o.y *= iv; o.z *= iv; o.w *= iv;
        gout[((size_t)(q0 + row) * HQ + h) * 32 + w * 4 + dg] = o;
    }
}

// ---- kernel 2: roco column sums from E scratch (memory-bound) ----
__global__ void __launch_bounds__(256, 8)
roco_colsum_kernel(float* __restrict__ roco, float* __restrict__ roco_sq)
{
    const int kt = blockIdx.x, h = blockIdx.y;
    const int k0 = kt * BN;
    const int tid = threadIdx.x;
    const int c = tid & 63, g = tid >> 6;          // 4 q-row groups

    float cs = 0.0f, cq = 0.0f;
    const float* Ebase = &E_scratch[((long long)h * QLEN) * QLEN + k0 + c];
    const float* ivb   = &invl_g[h * QLEN];
#pragma unroll 4
    for (int q = k0 + g; q < QLEN; q += 4) {
        float e = Ebase[(long long)q * QLEN];
        float p = e * ivb[q];
        cs += p;
        cq = fmaf(p, p, cq);
    }
    __shared__ float sc[4][64], sq[4][64];
    sc[g][c] = cs; sq[g][c] = cq;
    __syncthreads();
    if (tid < 64) {
        roco[h * QLEN + k0 + tid]    = (sc[0][tid] + sc[1][tid]) + (sc[2][tid] + sc[3][tid]);
        roco_sq[h * QLEN + k0 + tid] = (sq[0][tid] + sq[1][tid]) + (sq[2][tid] + sq[3][tid]);
    }
}

extern "C" void kernel_launch(void* const* d_in, const int* in_sizes, int n_in,
                              void* d_out, int out_size)
{
    const float* Qg = (const float*)d_in[0];
    const float* Kg = (const float*)d_in[1];
    const float* Vg = (const float*)d_in[2];
    float* Outg    = (float*)d_out;
    float* roco    = Outg + (size_t)QLEN * HQ * DDIM;   // 8388608
    float* roco_sq = roco + HQ * QLEN;                  // +65536

    cudaFuncSetAttribute(roco_fused_kernel,
                         cudaFuncAttributeMaxDynamicSharedMemorySize, SMEM_BYTES);

    dim3 grid1(QLEN / BM, HQ);      // (32, 32)
    roco_fused_kernel<<<grid1, NT, SMEM_BYTES>>>(Qg, Kg, Vg, Outg);

    dim3 grid2(QLEN / BN, HQ);      // (32, 32)
    roco_colsum_kernel<<<grid2, 256>>>(roco, roco_sq);
}

// round 5
// speedup vs baseline: 1.1444x; 1.0038x over previous
#include <cuda_runtime.h>
#include <math.h>

#define HQ   32
#define QLEN 2048
#define DDIM 128
#define BM   64
#define BN   64
#define NT   256

typedef unsigned long long u64;

// 512MB unnormalized exp(S) scratch + 256KB invl  (device globals = sanctioned scratch)
__device__ float E_scratch[(long long)HQ * QLEN * QLEN];
__device__ float invl_g[HQ * QLEN];

// ---- smem layout (float offsets), all rows padded to 132 floats ----
#define SQ_OFF  0          // [64][132]
#define SK_OFF  8448       // 2 x [64][132]
#define SK_BUF  8448
#define SV_OFF  25344      // 2 x [64][132]
#define SV_BUF  8448
#define SE_OFF  42240      // [64][132]  duplicated-pair E tile
#define RED_OFF 50688      // [4][64] rsum partials
#define INV_OFF 50944      // [64] invl
#define SMEM_FLOATS 51008
#define SMEM_BYTES (SMEM_FLOATS * 4)

#define FMA2(acc, a, b) asm("fma.rn.f32x2 %0, %1, %2, %0;" : "+l"(acc) : "l"(a), "l"(b))
#define PACK2(d, f)     asm("mov.b64 %0, {%1, %1};" : "=l"(d) : "f"(f))
#define UNPACK2(lo, hi, d) asm("mov.b64 {%0, %1}, %2;" : "=f"(lo), "=f"(hi) : "l"(d))
#define LDS128_2U64(lo, hi, addr) \
    asm("ld.shared.v2.b64 {%0, %1}, [%2];" : "=l"(lo), "=l"(hi) : "r"(addr))
#define STS128_2U64(addr, lo, hi) \
    asm volatile("st.shared.v2.b64 [%0], {%1, %2};" :: "r"(addr), "l"(lo), "l"(hi))
#define CPA16(dst, src) \
    asm volatile("cp.async.cg.shared.global [%0], [%1], 16;" :: "r"(dst), "l"(src))
#define CPC() asm volatile("cp.async.commit_group;" ::: "memory")
template<int N> __device__ __forceinline__ void cp_wait() {
    asm volatile("cp.async.wait_group %0;" :: "n"(N) : "memory");
}

__global__ void __launch_bounds__(NT, 1)
roco_fused_kernel(const float* __restrict__ Qg, const float* __restrict__ Kg,
                  const float* __restrict__ Vg, float* __restrict__ Outg)
{
    extern __shared__ float smem[];
    const unsigned sb  = (unsigned)__cvta_generic_to_shared(smem);
    const unsigned sQb = sb + SQ_OFF * 4;
    const unsigned sKb = sb + SK_OFF * 4;
    const unsigned sVb = sb + SV_OFF * 4;
    const unsigned sEb = sb + SE_OFF * 4;
    float* redb  = smem + RED_OFF;
    float* invls = smem + INV_OFF;

    const int h  = blockIdx.y;
    const int qt = (gridDim.x - 1) - blockIdx.x;   // heavy tiles first
    const int q0 = qt * BM;
    const int tid = threadIdx.x;
    const int w   = tid >> 5;
    const int l   = tid & 31;
    const float scale = 0.08838834764831845f;      // 1/sqrt(128)

    // QK mapping: warp (wm,wn) tile 32m x 16n; lane (li,lj) owns 4m x 4n
    const int wm = w >> 2, wn = w & 3;
    const int li = l >> 2, lj = l & 3;
    const int mBase = wm * 32 + li * 4;            // + r (0..3)
    const int nBase = wn * 16 + lj * 4;            // + c (0..3)

    // PV mapping: warp w owns d-cols [w*16, w*16+16); lane (mg,dg): rows s*8+mg, d = w*16+dg*4
    const int mg = l >> 2, dg = l & 3;
    const int dOff = w * 16 + dg * 4;

    const float4* gq = reinterpret_cast<const float4*>(Qg);
    const float4* gk = reinterpret_cast<const float4*>(Kg);
    const float4* gv = reinterpret_cast<const float4*>(Vg);

    // ---- load Q tile (padded rows of 132 floats) ----
    float4* sQ4 = reinterpret_cast<float4*>(smem);
    for (int i = tid; i < BM * 32; i += NT) {
        int m = i >> 5, d4 = i & 31;
        sQ4[m * 33 + d4] = gq[((size_t)(q0 + m) * HQ + h) * 32 + d4];
    }

    // ---- prologue: prefetch K,V tile 0 ----
    for (int i = tid; i < BN * 32; i += NT) {
        int n = i >> 5, d4 = i & 31;
        CPA16(sKb + (n * 132 + d4 * 4) * 4, &gk[((size_t)n * HQ + h) * 32 + d4]);
        CPA16(sVb + (n * 132 + d4 * 4) * 4, &gv[((size_t)n * HQ + h) * 32 + d4]);
    }
    CPC();

    float rpart[4];
#pragma unroll
    for (int r = 0; r < 4; r++) rpart[r] = 0.0f;
    u64 o2[8][2];
#pragma unroll
    for (int s = 0; s < 8; s++) { o2[s][0] = 0ull; o2[s][1] = 0ull; }

    for (int kt = 0; kt <= qt; ++kt) {
        const int cur = kt & 1;
        const int k0 = kt * BN;
        __syncthreads();                           // (a) prev PV done
        if (kt < qt) {
            const int k1 = (kt + 1) * BN;
            for (int i = tid; i < BN * 32; i += NT) {
                int n = i >> 5, d4 = i & 31;
                CPA16(sKb + ((cur ^ 1) * SK_BUF + n * 132 + d4 * 4) * 4,
                      &gk[((size_t)(k1 + n) * HQ + h) * 32 + d4]);
                CPA16(sVb + ((cur ^ 1) * SV_BUF + n * 132 + d4 * 4) * 4,
                      &gv[((size_t)(k1 + n) * HQ + h) * 32 + d4]);
            }
            CPC();
            cp_wait<1>();
        } else {
            cp_wait<0>();
        }
        __syncthreads();                           // (b) cur K,V visible

        // ================= QK^T =================
        u64 acc2[4][4];
#pragma unroll
        for (int r = 0; r < 4; r++)
#pragma unroll
            for (int c = 0; c < 4; c++) acc2[r][c] = 0ull;

        const unsigned qA = sQb + (mBase * 132) * 4;
        const unsigned kA = sKb + (cur * SK_BUF + nBase * 132) * 4;

#pragma unroll 2
        for (int d4 = 0; d4 < 32; ++d4) {
            u64 qa[4][2], kb[4][2];
#pragma unroll
            for (int r = 0; r < 4; r++)
                LDS128_2U64(qa[r][0], qa[r][1], qA + (r * 132 + d4 * 4) * 4);
#pragma unroll
            for (int c = 0; c < 4; c++)
                LDS128_2U64(kb[c][0], kb[c][1], kA + (c * 132 + d4 * 4) * 4);
#pragma unroll
            for (int r = 0; r < 4; r++)
#pragma unroll
                for (int c = 0; c < 4; c++) {
                    FMA2(acc2[r][c], qa[r][0], kb[c][0]);
                    FMA2(acc2[r][c], qa[r][1], kb[c][1]);
                }
        }

        // ============ epilogue: exp, E store, dup STS, rsum ============
#pragma unroll
        for (int r = 0; r < 4; r++) {
            const int qrow = q0 + mBase + r;
            float ev[4];
#pragma unroll
            for (int c = 0; c < 4; c++) {
                float lo, hi;
                UNPACK2(lo, hi, acc2[r][c]);
                float s = (lo + hi) * scale;
                ev[c] = (k0 + nBase + c <= qrow) ? __expf(s) : 0.0f;
            }
            rpart[r] += (ev[0] + ev[1]) + (ev[2] + ev[3]);
            // global E store
            *reinterpret_cast<float4*>(
                &E_scratch[((long long)(h * QLEN + qrow)) * QLEN + k0 + nBase]) =
                make_float4(ev[0], ev[1], ev[2], ev[3]);
            // duplicated-pair smem store: sE[m][2k]=sE[m][2k+1]=e[k]
            u64 p0, p1, p2, p3;
            PACK2(p0, ev[0]); PACK2(p1, ev[1]); PACK2(p2, ev[2]); PACK2(p3, ev[3]);
            const unsigned eA = sEb + ((mBase + r) * 132 + wn * 32 + lj * 8) * 4;
            STS128_2U64(eA, p0, p1);
            STS128_2U64(eA + 16, p2, p3);
        }
        __syncthreads();                           // (c) sE visible

        // ================= PV (d-split, unnormalized) =================
        const unsigned vA = sVb + (cur * SV_BUF) * 4 + dOff * 4;
        const unsigned eA = sEb + mg * 132 * 4;
#pragma unroll 2
        for (int j = 0; j < 32; ++j) {             // n pair {2j, 2j+1}
            u64 v0a, v0b, v1a, v1b;
            LDS128_2U64(v0a, v0b, vA + ((2 * j) * 132) * 4);
            LDS128_2U64(v1a, v1b, vA + ((2 * j + 1) * 132) * 4);
#pragma unroll
            for (int s = 0; s < 8; s++) {
                u64 e0, e1;
                LDS128_2U64(e0, e1, eA + (s * 8 * 132 + 4 * j) * 4);
                FMA2(o2[s][0], e0, v0a); FMA2(o2[s][1], e0, v0b);
                FMA2(o2[s][0], e1, v1a); FMA2(o2[s][1], e1, v1b);
            }
        }
    }

    // ---- rsum reduction, invl, O scale+store ----
#pragma unroll
    for (int r = 0; r < 4; r++) {
        rpart[r] += __shfl_xor_sync(0xffffffffu, rpart[r], 1);
        rpart[r] += __shfl_xor_sync(0xffffffffu, rpart[r], 2);
    }
    if (lj == 0) {
#pragma unroll
        for (int r = 0; r < 4; r++) redb[wn * 64 + mBase + r] = rpart[r];
    }
    __syncthreads();
    if (tid < 64) {
        float s = redb[tid] + redb[64 + tid] + redb[128 + tid] + redb[192 + tid];
        float iv = 1.0f / s;
        invls[tid] = iv;
        invl_g[h * QLEN + q0 + tid] = iv;
    }
    __syncthreads();

    float4* gout = reinterpret_cast<float4*>(Outg);
#pragma unroll
    for (int s = 0; s < 8; s++) {
        const int row = s * 8 + mg;
        const float iv = invls[row];
        float4 o;
        UNPACK2(o.x, o.y, o2[s][0]);
        UNPACK2(o.z, o.w, o2[s][1]);
        o.x *= iv; o.y *= iv; o.z *= iv; o.w *= iv;
        gout[((size_t)(q0 + row) * HQ + h) * 32 + w * 4 + dg] = o;
    }
}

// ---- kernel 2: roco column sums from E scratch (memory-bound) ----
__global__ void __launch_bounds__(256, 8)
roco_colsum_kernel(float* __restrict__ roco, float* __restrict__ roco_sq)
{
    const int kt = blockIdx.x, h = blockIdx.y;
    const int k0 = kt * BN;
    const int tid = threadIdx.x;
    const int c = tid & 63, g = tid >> 6;          // 4 q-row groups

    float cs = 0.0f, cq = 0.0f;
    const float* Ebase = &E_scratch[((long long)h * QLEN) * QLEN + k0 + c];
    const float* ivb   = &invl_g[h * QLEN];
#pragma unroll 4
    for (int q = k0 + g; q < QLEN; q += 4) {
        float e = Ebase[(long long)q * QLEN];
        float p = e * ivb[q];
        cs += p;
        cq = fmaf(p, p, cq);
    }
    __shared__ float sc[4][64], sq[4][64];
    sc[g][c] = cs; sq[g][c] = cq;
    __syncthreads();
    if (tid < 64) {
        roco[h * QLEN + k0 + tid]    = (sc[0][tid] + sc[1][tid]) + (sc[2][tid] + sc[3][tid]);
        roco_sq[h * QLEN + k0 + tid] = (sq[0][tid] + sq[1][tid]) + (sq[2][tid] + sq[3][tid]);
    }
}

extern "C" void kernel_launch(void* const* d_in, const int* in_sizes, int n_in,
                              void* d_out, int out_size)
{
    const float* Qg = (const float*)d_in[0];
    const float* Kg = (const float*)d_in[1];
    const float* Vg = (const float*)d_in[2];
    float* Outg    = (float*)d_out;
    float* roco    = Outg + (size_t)QLEN * HQ * DDIM;   // 8388608
    float* roco_sq = roco + HQ * QLEN;                  // +65536

    cudaFuncSetAttribute(roco_fused_kernel,
                         cudaFuncAttributeMaxDynamicSharedMemorySize, SMEM_BYTES);

    dim3 grid1(QLEN / BM, HQ);      // (32, 32)
    roco_fused_kernel<<<grid1, NT, SMEM_BYTES>>>(Qg, Kg, Vg, Outg);

    dim3 grid2(QLEN / BN, HQ);      // (32, 32)
    roco_colsum_kernel<<<grid2, 256>>>(roco, roco_sq);
}

// round 8
// speedup vs baseline: 3.5362x; 3.0901x over previous
#include <cuda_runtime.h>
#include <cstdint>

#define HQ    32
#define QLEN  2048
#define KVLEN 2048

// [h][kv][q] unnormalized exp-scores
__device__ float E_scratch[(size_t)HQ * KVLEN * QLEN];
__device__ float invl_g[HQ * QLEN];

// ---- smem byte offsets ----
#define SM_RED   0            // 2*128 floats
#define SM_Q     2048         // [128][PQ] fp32
#define SM_SLOT0 71680        // 3 rotating K/V slots
#define SLOT_SZ  34816        // 64*136*4
#define SM_E     176128       // [128][PE]
#define SM_TOTAL 212992

#define PQ 136
#define PK 136
#define PVP 132
#define PE 72

#define CPA16(dst, src) \
    asm volatile("cp.async.cg.shared.global [%0], [%1], 16;" :: "r"(dst), "l"(src))
#define CPC() asm volatile("cp.async.commit_group;" ::: "memory")
#define CPWAIT(N) asm volatile("cp.async.wait_group %0;" :: "n"(N) : "memory")

#define MMA_TF32(c, a0, a1, a2, a3, b0, b1) \
    asm volatile("mma.sync.aligned.m16n8k8.row.col.f32.tf32.tf32.f32 " \
        "{%0,%1,%2,%3},{%4,%5,%6,%7},{%8,%9},{%0,%1,%2,%3};" \
        : "+f"((c)[0]), "+f"((c)[1]), "+f"((c)[2]), "+f"((c)[3]) \
        : "r"(a0), "r"(a1), "r"(a2), "r"(a3), "r"(b0), "r"(b1))

#define CVT_RNA(u, f) asm("cvt.rna.tf32.f32 %0, %1;" : "=r"(u) : "f"(f))

__device__ __forceinline__ uint32_t smem_u32(const void* p){
    uint32_t a;
    asm("{ .reg .u64 t; cvta.to.shared.u64 t, %1; cvt.u32.u64 %0, t; }" : "=r"(a) : "l"(p));
    return a;
}

__device__ __forceinline__ void load_k_tile(char* sm, int slot, const float4* gk,
                                            int k0, int h, int tid){
    char* base = sm + SM_SLOT0 + slot * SLOT_SZ;
    for (int i = tid; i < 64 * 32; i += 256){
        int n = i >> 5, c = i & 31;
        CPA16(smem_u32(base + n * (PK * 4) + c * 16),
              &gk[((size_t)(k0 + n) * HQ + h) * 32 + c]);
    }
}
__device__ __forceinline__ void load_v_tile(char* sm, int slot, const float4* gv,
                                            int k0, int h, int tid){
    char* base = sm + SM_SLOT0 + slot * SLOT_SZ;
    for (int i = tid; i < 64 * 32; i += 256){
        int n = i >> 5, c = i & 31;
        CPA16(smem_u32(base + n * (PVP * 4) + c * 16),
              &gv[((size_t)(k0 + n) * HQ + h) * 32 + c]);
    }
}

// round a [rows][128] fp32 tile (pitch in floats, multiple of 4) to tf32 in place
__device__ __forceinline__ void rna_round_tile(float* base, int pitchFloats,
                                               int rows, int tid){
    for (int i = tid; i < rows * 32; i += 256){
        int r = i >> 5, c = i & 31;
        float4* p = reinterpret_cast<float4*>(base + r * pitchFloats) + c;
        float4 v = *p;
        uint32_t x, y, z, w;
        CVT_RNA(x, v.x); CVT_RNA(y, v.y); CVT_RNA(z, v.z); CVT_RNA(w, v.w);
        *reinterpret_cast<uint4*>(p) = make_uint4(x, y, z, w);
    }
}

__global__ void __launch_bounds__(256, 1)
attn_mma_kernel(const float* __restrict__ Qg, const float* __restrict__ Kg,
                const float* __restrict__ Vg, float* __restrict__ Outg)
{
    extern __shared__ char sm[];
    const int tid = threadIdx.x, w = tid >> 5, lid = tid & 31;
    const int tq = lid >> 2, tr = lid & 3;
    const int h = blockIdx.y;
    const int qi = (gridDim.x - 1) - blockIdx.x;       // heavy tiles first
    const int q0 = qi * 128;
    const int nt = 2 * qi + 2;
    const float scale = 0.08838834764831845f;

    const int wq = w & 3;        // 32-row block (shared by QK and PV)
    const int wn = w >> 2;       // QK: 32-col block; PV: 64-d block

    float* red = (float*)(sm + SM_RED);
    float* sQ  = (float*)(sm + SM_Q);
    float* sE  = (float*)(sm + SM_E);

    const float4* gq = (const float4*)Qg;
    const float4* gk = (const float4*)Kg;
    const float4* gv = (const float4*)Vg;

    // ---- prologue: Q + K(0) (group 1), V(0) (group 2) ----
    for (int i = tid; i < 128 * 32; i += 256){
        int m = i >> 5, c = i & 31;
        CPA16(smem_u32(sm + SM_Q + m * (PQ * 4) + c * 16),
              &gq[((size_t)(q0 + m) * HQ + h) * 32 + c]);
    }
    load_k_tile(sm, 0, gk, 0, h, tid);
    CPC();
    load_v_tile(sm, 1, gv, 0, h, tid);
    CPC();

    float acco[2][8][4];
    float rsum[4] = {0.f, 0.f, 0.f, 0.f};
#pragma unroll
    for (int mf = 0; mf < 2; ++mf)
#pragma unroll
        for (int nf = 0; nf < 8; ++nf)
#pragma unroll
            for (int x = 0; x < 4; ++x) acco[mf][nf][x] = 0.f;

    int ks = 0, vs = 1;

    for (int t = 0; t < nt; ++t){
        const int k0 = t * 64;

        CPWAIT(1);               // K(t) ready (V(t) may be newest pending)
        __syncthreads();
        if (t + 1 < nt){ load_k_tile(sm, 3 - ks - vs, gk, (t + 1) * 64, h, tid); CPC(); }

        // round freshly-landed K tile (and Q once) to tf32-RNA in place
        if (t == 0) rna_round_tile(sQ, PQ, 128, tid);
        rna_round_tile((float*)(sm + SM_SLOT0 + ks * SLOT_SZ), PK, 64, tid);
        __syncthreads();

        // ================= QK^T (tf32 MMA) =================
        float accs[2][4][4];
#pragma unroll
        for (int mf = 0; mf < 2; ++mf)
#pragma unroll
            for (int nf = 0; nf < 4; ++nf)
#pragma unroll
                for (int x = 0; x < 4; ++x) accs[mf][nf][x] = 0.f;

        const float* Kb = (const float*)(sm + SM_SLOT0 + ks * SLOT_SZ);
#pragma unroll
        for (int j = 0; j < 16; ++j){
            const int col = j * 8 + 2 * tr;        // k-lane c -> global d = 8j + 2(c%4) + c/4
            uint2 a[2][2], b[4];
#pragma unroll
            for (int mf = 0; mf < 2; ++mf)
#pragma unroll
                for (int hf = 0; hf < 2; ++hf)
                    a[mf][hf] = *(const uint2*)(sQ + (wq*32 + mf*16 + hf*8 + tq) * PQ + col);
#pragma unroll
            for (int nf = 0; nf < 4; ++nf)
                b[nf] = *(const uint2*)(Kb + (wn*32 + nf*8 + tq) * PK + col);
#pragma unroll
            for (int mf = 0; mf < 2; ++mf)
#pragma unroll
                for (int nf = 0; nf < 4; ++nf)
                    MMA_TF32(accs[mf][nf],
                             a[mf][0].x, a[mf][1].x, a[mf][0].y, a[mf][1].y,
                             b[nf].x, b[nf].y);
        }

        // ============ epilogue: exp, rsum, E (smem tf32 + global fp32) ============
#pragma unroll
        for (int mf = 0; mf < 2; ++mf)
#pragma unroll
            for (int nf = 0; nf < 4; ++nf){
                const int kvb = k0 + wn*32 + nf*8 + 2*tr;
#pragma unroll
                for (int hf = 0; hf < 2; ++hf){
                    const int row  = wq*32 + mf*16 + hf*8 + tq;
                    const int qrow = q0 + row;
                    float e0 = (kvb     <= qrow) ? __expf(accs[mf][nf][hf*2    ] * scale) : 0.f;
                    float e1 = (kvb + 1 <= qrow) ? __expf(accs[mf][nf][hf*2 + 1] * scale) : 0.f;
                    rsum[mf*2 + hf] += e0 + e1;
                    uint32_t r0, r1;
                    CVT_RNA(r0, e0); CVT_RNA(r1, e1);
                    *(uint2*)(sE + row * PE + wn*32 + nf*8 + 2*tr) = make_uint2(r0, r1);
                    float* Eg = &E_scratch[((size_t)h * KVLEN + kvb) * QLEN + qrow];
                    Eg[0] = e0; Eg[QLEN] = e1;
                }
            }

        if (t + 1 < nt) { CPWAIT(1); } else { CPWAIT(0); }   // V(t) ready
        __syncthreads();                                      // E visible; K slot free
        if (t + 1 < nt){ load_v_tile(sm, ks, gv, (t + 1) * 64, h, tid); CPC(); }

        // round V tile to tf32-RNA in place
        rna_round_tile((float*)(sm + SM_SLOT0 + vs * SLOT_SZ), PVP, 64, tid);
        __syncthreads();

        // ================= PV (accumulate O) =================
        const float* Vb = (const float*)(sm + SM_SLOT0 + vs * SLOT_SZ);
#pragma unroll
        for (int j = 0; j < 8; ++j){
            const int kc = j * 8 + 2 * tr;
            uint2 a[2][2];
#pragma unroll
            for (int mf = 0; mf < 2; ++mf)
#pragma unroll
                for (int hf = 0; hf < 2; ++hf)
                    a[mf][hf] = *(const uint2*)(sE + (wq*32 + mf*16 + hf*8 + tq) * PE + kc);
            uint32_t b0[8], b1[8];
#pragma unroll
            for (int nf = 0; nf < 8; ++nf){
                const int d = wn*64 + nf*8 + tq;
                b0[nf] = __float_as_uint(Vb[kc * PVP + d]);
                b1[nf] = __float_as_uint(Vb[(kc + 1) * PVP + d]);
            }
#pragma unroll
            for (int mf = 0; mf < 2; ++mf)
#pragma unroll
                for (int nf = 0; nf < 8; ++nf)
                    MMA_TF32(acco[mf][nf],
                             a[mf][0].x, a[mf][1].x, a[mf][0].y, a[mf][1].y,
                             b0[nf], b1[nf]);
        }

        const int nks = 3 - ks - vs; vs = ks; ks = nks;
    }

    // ---- row sums -> invl ----
#pragma unroll
    for (int r = 0; r < 4; ++r){
        rsum[r] += __shfl_xor_sync(0xffffffffu, rsum[r], 1);
        rsum[r] += __shfl_xor_sync(0xffffffffu, rsum[r], 2);
    }
    if (tr == 0){
#pragma unroll
        for (int r = 0; r < 4; ++r)
            red[wn * 128 + wq*32 + r*8 + tq] = rsum[r];
    }
    __syncthreads();
    float inv[4];
#pragma unroll
    for (int r = 0; r < 4; ++r){
        const int row = wq*32 + r*8 + tq;
        inv[r] = 1.0f / (red[row] + red[128 + row]);
    }
    if (wn == 0 && tr == 0){
#pragma unroll
        for (int r = 0; r < 4; ++r)
            invl_g[h * QLEN + q0 + wq*32 + r*8 + tq] = inv[r];
    }

    // ---- O writeout ----
#pragma unroll
    for (int mf = 0; mf < 2; ++mf)
#pragma unroll
        for (int hf = 0; hf < 2; ++hf){
            const int row = wq*32 + mf*16 + hf*8 + tq;
            const float iv = inv[mf*2 + hf];
#pragma unroll
            for (int nf = 0; nf < 8; ++nf){
                const int d = wn*64 + nf*8 + 2*tr;
                *(float2*)&Outg[((size_t)(q0 + row) * HQ + h) * 128 + d] =
                    make_float2(acco[mf][nf][hf*2] * iv, acco[mf][nf][hf*2 + 1] * iv);
            }
        }
}

// ---- kernel 2: roco column sums, streaming over E[h][kv][q] ----
__global__ void __launch_bounds__(256, 8)
roco_colsum_kernel(float* __restrict__ roco, float* __restrict__ roco_sq)
{
    const int h = blockIdx.y;
    const int g = threadIdx.x >> 5, l = threadIdx.x & 31;
    const int kv = blockIdx.x * 8 + g;
    const int qs4 = ((kv >> 7) << 7) >> 2;     // first valid q / 4 (q-tiles of 128)

    const float4* Eb  = (const float4*)&E_scratch[((size_t)h * KVLEN + kv) * QLEN];
    const float4* ivb = (const float4*)&invl_g[h * QLEN];

    float cs = 0.0f, cq = 0.0f;
    for (int q4 = qs4 + l; q4 < QLEN / 4; q4 += 32){
        float4 e  = Eb[q4];
        float4 iv = ivb[q4];
        float p0 = e.x * iv.x, p1 = e.y * iv.y, p2 = e.z * iv.z, p3 = e.w * iv.w;
        cs += (p0 + p1) + (p2 + p3);
        cq = fmaf(p0, p0, cq); cq = fmaf(p1, p1, cq);
        cq = fmaf(p2, p2, cq); cq = fmaf(p3, p3, cq);
    }
#pragma unroll
    for (int off = 16; off > 0; off >>= 1){
        cs += __shfl_xor_sync(0xffffffffu, cs, off);
        cq += __shfl_xor_sync(0xffffffffu, cq, off);
    }
    if (l == 0){
        roco[h * QLEN + kv]    = cs;
        roco_sq[h * QLEN + kv] = cq;
    }
}

extern "C" void kernel_launch(void* const* d_in, const int* in_sizes, int n_in,
                              void* d_out, int out_size)
{
    const float* Qg = (const float*)d_in[0];
    const float* Kg = (const float*)d_in[1];
    const float* Vg = (const float*)d_in[2];
    float* Outg    = (float*)d_out;
    float* roco    = Outg + (size_t)QLEN * HQ * 128;    // 8388608
    float* roco_sq = roco + HQ * QLEN;                  // +65536

    cudaFuncSetAttribute(attn_mma_kernel,
                         cudaFuncAttributeMaxDynamicSharedMemorySize, SM_TOTAL);

    dim3 grid1(QLEN / 128, HQ);     // (16, 32)
    attn_mma_kernel<<<grid1, 256, SM_TOTAL>>>(Qg, Kg, Vg, Outg);

    dim3 grid2(KVLEN / 8, HQ);      // (256, 32)
    roco_colsum_kernel<<<grid2, 256>>>(roco, roco_sq);
}

// round 10
// speedup vs baseline: 3.8185x; 1.0798x over previous
#include <cuda_runtime.h>
#include <cuda_fp16.h>
#include <cstdint>

#define HQ    32
#define QLEN  2048
#define KVLEN 2048

// rounded, head-major copies of inputs
__device__ float Qp[(size_t)HQ * QLEN * 128];
__device__ float Kp[(size_t)HQ * KVLEN * 128];
__device__ float Vp[(size_t)HQ * KVLEN * 128];
// [h][q][kv] unnormalized exp-scores, fp16
__device__ __half Ep[(size_t)HQ * QLEN * KVLEN];
__device__ float invl_g[HQ * QLEN];

// ---- smem byte offsets ----
#define SM_RED   0
#define SM_Q     2048
#define SM_SLOT0 71680
#define SLOT_SZ  34816        // 64*136*4
#define SM_E     176128       // [128][PE]
#define SM_TOTAL 212992

#define PQ 136
#define PK 136
#define PVP 132
#define PE 72

#define CPA16(dst, src) \
    asm volatile("cp.async.cg.shared.global [%0], [%1], 16;" :: "r"(dst), "l"(src))
#define CPC() asm volatile("cp.async.commit_group;" ::: "memory")
#define CPWAIT(N) asm volatile("cp.async.wait_group %0;" :: "n"(N) : "memory")

#define MMA_TF32(c, a0, a1, a2, a3, b0, b1) \
    asm volatile("mma.sync.aligned.m16n8k8.row.col.f32.tf32.tf32.f32 " \
        "{%0,%1,%2,%3},{%4,%5,%6,%7},{%8,%9},{%0,%1,%2,%3};" \
        : "+f"((c)[0]), "+f"((c)[1]), "+f"((c)[2]), "+f"((c)[3]) \
        : "r"(a0), "r"(a1), "r"(a2), "r"(a3), "r"(b0), "r"(b1))

#define CVT_RNA(u, f) asm("cvt.rna.tf32.f32 %0, %1;" : "=r"(u) : "f"(f))
// pack (lo, hi) floats into f16x2 word: lo -> low half
#define PACK_F16X2(u, lo, hi) \
    asm("cvt.rn.f16x2.f32 %0, %1, %2;" : "=r"(u) : "f"(hi), "f"(lo))

__device__ __forceinline__ uint32_t smem_u32(const void* p){
    uint32_t a;
    asm("{ .reg .u64 t; cvta.to.shared.u64 t, %1; cvt.u32.u64 %0, t; }" : "=r"(a) : "l"(p));
    return a;
}

// ---- kernel 0a: round Q/K/V to tf32-RNA, transpose to [h][tok][d] ----
__global__ void __launch_bounds__(256, 4)
preround_kernel(const float* __restrict__ Qg, const float* __restrict__ Kg,
                const float* __restrict__ Vg)
{
    const int z = blockIdx.z, h = blockIdx.y;
    const int r = blockIdx.x * 8 + (threadIdx.x >> 5);
    const int c = threadIdx.x & 31;
    const float4* src = (const float4*)(z == 0 ? Qg : (z == 1 ? Kg : Vg));
    uint4* dst = (uint4*)(z == 0 ? Qp : (z == 1 ? Kp : Vp));
    float4 v = src[((size_t)r * HQ + h) * 32 + c];
    uint4 u;
    CVT_RNA(u.x, v.x); CVT_RNA(u.y, v.y); CVT_RNA(u.z, v.z); CVT_RNA(u.w, v.w);
    dst[((size_t)h * QLEN + r) * 32 + c] = u;
}

// ---- kernel 0b: zero roco outputs ----
__global__ void zero_kernel(float* __restrict__ p, int n)
{
    int i = blockIdx.x * blockDim.x + threadIdx.x;
    if (i < n) p[i] = 0.0f;
}

__device__ __forceinline__ void load_k_tile(char* sm, int slot, const float4* gk,
                                            int k0, int h, int tid){
    char* base = sm + SM_SLOT0 + slot * SLOT_SZ;
    for (int i = tid; i < 64 * 32; i += 256){
        int n = i >> 5, c = i & 31;
        CPA16(smem_u32(base + n * (PK * 4) + c * 16),
              &gk[((size_t)h * KVLEN + k0 + n) * 32 + c]);
    }
}
__device__ __forceinline__ void load_v_tile(char* sm, int slot, const float4* gv,
                                            int k0, int h, int tid){
    char* base = sm + SM_SLOT0 + slot * SLOT_SZ;
    for (int i = tid; i < 64 * 32; i += 256){
        int n = i >> 5, c = i & 31;
        CPA16(smem_u32(base + n * (PVP * 4) + c * 16),
              &gv[((size_t)h * KVLEN + k0 + n) * 32 + c]);
    }
}

__global__ void __launch_bounds__(256, 1)
attn_mma_kernel(float* __restrict__ Outg)
{
    extern __shared__ char sm[];
    const int tid = threadIdx.x, w = tid >> 5, lid = tid & 31;
    const int tq = lid >> 2, tr = lid & 3;
    const int h = blockIdx.y;
    const int qi = (gridDim.x - 1) - blockIdx.x;       // heavy tiles first
    const int q0 = qi * 128;
    const int nt = 2 * qi + 2;
    const float scale = 0.08838834764831845f;

    const int wq = w & 3;        // 32-row block
    const int wn = w >> 2;       // QK: 32-col block; PV: 64-d block

    float* red = (float*)(sm + SM_RED);
    float* sQ  = (float*)(sm + SM_Q);
    float* sE  = (float*)(sm + SM_E);

    const float4* gq = (const float4*)Qp;
    const float4* gk = (const float4*)Kp;
    const float4* gv = (const float4*)Vp;

    // ---- prologue: Q + K(0) (group), V(0) (group) ----
    for (int i = tid; i < 128 * 32; i += 256){
        int m = i >> 5, c = i & 31;
        CPA16(smem_u32(sm + SM_Q + m * (PQ * 4) + c * 16),
              &gq[((size_t)h * QLEN + q0 + m) * 32 + c]);
    }
    load_k_tile(sm, 0, gk, 0, h, tid);
    CPC();
    load_v_tile(sm, 1, gv, 0, h, tid);
    CPC();

    float acco[2][8][4];
    float rsum[4] = {0.f, 0.f, 0.f, 0.f};
#pragma unroll
    for (int mf = 0; mf < 2; ++mf)
#pragma unroll
        for (int nf = 0; nf < 8; ++nf)
#pragma unroll
            for (int x = 0; x < 4; ++x) acco[mf][nf][x] = 0.f;

    int ks = 0, vs = 1;

    for (int t = 0; t < nt; ++t){
        const int k0 = t * 64;

        CPWAIT(1);               // K(t) ready
        __syncthreads();         // + prev PV done (frees the rotation slot)
        if (t + 1 < nt){ load_k_tile(sm, 3 - ks - vs, gk, (t + 1) * 64, h, tid); CPC(); }

        // ================= QK^T (tf32 MMA) =================
        float accs[2][4][4];
#pragma unroll
        for (int mf = 0; mf < 2; ++mf)
#pragma unroll
            for (int nf = 0; nf < 4; ++nf)
#pragma unroll
                for (int x = 0; x < 4; ++x) accs[mf][nf][x] = 0.f;

        const float* Kb = (const float*)(sm + SM_SLOT0 + ks * SLOT_SZ);
#pragma unroll
        for (int j = 0; j < 16; ++j){
            const int col = j * 8 + 2 * tr;        // k-lane c -> global d = 8j + 2(c%4) + c/4
            uint2 a[2][2], b[4];
#pragma unroll
            for (int mf = 0; mf < 2; ++mf)
#pragma unroll
                for (int hf = 0; hf < 2; ++hf)
                    a[mf][hf] = *(const uint2*)(sQ + (wq*32 + mf*16 + hf*8 + tq) * PQ + col);
#pragma unroll
            for (int nf = 0; nf < 4; ++nf)
                b[nf] = *(const uint2*)(Kb + (wn*32 + nf*8 + tq) * PK + col);
#pragma unroll
            for (int mf = 0; mf < 2; ++mf)
#pragma unroll
                for (int nf = 0; nf < 4; ++nf)
                    MMA_TF32(accs[mf][nf],
                             a[mf][0].x, a[mf][1].x, a[mf][0].y, a[mf][1].y,
                             b[nf].x, b[nf].y);
        }

        // ============ epilogue: exp, rsum, E (smem tf32 + global fp16) ============
#pragma unroll
        for (int mf = 0; mf < 2; ++mf)
#pragma unroll
            for (int nf = 0; nf < 4; ++nf){
                const int kvb = k0 + wn*32 + nf*8 + 2*tr;
#pragma unroll
                for (int hf = 0; hf < 2; ++hf){
                    const int row  = wq*32 + mf*16 + hf*8 + tq;
                    const int qrow = q0 + row;
                    float e0 = (kvb     <= qrow) ? __expf(accs[mf][nf][hf*2    ] * scale) : 0.f;
                    float e1 = (kvb + 1 <= qrow) ? __expf(accs[mf][nf][hf*2 + 1] * scale) : 0.f;
                    rsum[mf*2 + hf] += e0 + e1;
                    uint32_t r0, r1;
                    CVT_RNA(r0, e0); CVT_RNA(r1, e1);
                    *(uint2*)(sE + row * PE + wn*32 + nf*8 + 2*tr) = make_uint2(r0, r1);
                    uint32_t pk;
                    PACK_F16X2(pk, e0, e1);
                    *(uint32_t*)&Ep[((size_t)h * QLEN + qrow) * KVLEN + kvb] = pk;
                }
            }

        if (t + 1 < nt) { CPWAIT(1); } else { CPWAIT(0); }   // V(t) ready
        __syncthreads();                                      // E visible; slot free
        if (t + 1 < nt){ load_v_tile(sm, ks, gv, (t + 1) * 64, h, tid); CPC(); }

        // ================= PV (accumulate O) =================
        const float* Vb = (const float*)(sm + SM_SLOT0 + vs * SLOT_SZ);
#pragma unroll
        for (int j = 0; j < 8; ++j){
            const int kc = j * 8 + 2 * tr;
            uint2 a[2][2];
#pragma unroll
            for (int mf = 0; mf < 2; ++mf)
#pragma unroll
                for (int hf = 0; hf < 2; ++hf)
                    a[mf][hf] = *(const uint2*)(sE + (wq*32 + mf*16 + hf*8 + tq) * PE + kc);
            uint32_t b0[8], b1[8];
#pragma unroll
            for (int nf = 0; nf < 8; ++nf){
                const int d = wn*64 + nf*8 + tq;
                b0[nf] = __float_as_uint(Vb[kc * PVP + d]);
                b1[nf] = __float_as_uint(Vb[(kc + 1) * PVP + d]);
            }
#pragma unroll
            for (int mf = 0; mf < 2; ++mf)
#pragma unroll
                for (int nf = 0; nf < 8; ++nf)
                    MMA_TF32(acco[mf][nf],
                             a[mf][0].x, a[mf][1].x, a[mf][0].y, a[mf][1].y,
                             b0[nf], b1[nf]);
        }

        const int nks = 3 - ks - vs; vs = ks; ks = nks;
    }

    // ---- row sums -> invl ----
#pragma unroll
    for (int r = 0; r < 4; ++r){
        rsum[r] += __shfl_xor_sync(0xffffffffu, rsum[r], 1);
        rsum[r] += __shfl_xor_sync(0xffffffffu, rsum[r], 2);
    }
    if (tr == 0){
#pragma unroll
        for (int r = 0; r < 4; ++r)
            red[wn * 128 + wq*32 + r*8 + tq] = rsum[r];
    }
    __syncthreads();
    float inv[4];
#pragma unroll
    for (int r = 0; r < 4; ++r){
        const int row = wq*32 + r*8 + tq;
        inv[r] = 1.0f / (red[row] + red[128 + row]);
    }
    if (wn == 0 && tr == 0){
#pragma unroll
        for (int r = 0; r < 4; ++r)
            invl_g[h * QLEN + q0 + wq*32 + r*8 + tq] = inv[r];
    }

    // ---- O writeout ----
#pragma unroll
    for (int mf = 0; mf < 2; ++mf)
#pragma unroll
        for (int hf = 0; hf < 2; ++hf){
            const int row = wq*32 + mf*16 + hf*8 + tq;
            const float iv = inv[mf*2 + hf];
#pragma unroll
            for (int nf = 0; nf < 8; ++nf){
                const int d = wn*64 + nf*8 + 2*tr;
                *(float2*)&Outg[((size_t)(q0 + row) * HQ + h) * 128 + d] =
                    make_float2(acco[mf][nf][hf*2] * iv, acco[mf][nf][hf*2 + 1] * iv);
            }
        }
}

// ---- kernel 2: roco column sums over fp16 E[h][q][kv], q-chunked ----
__global__ void __launch_bounds__(256, 8)
roco_colsum_kernel(float* __restrict__ roco, float* __restrict__ roco_sq)
{
    __shared__ float ivs[512];
    const int h = blockIdx.y, z = blockIdx.z;
    const int qlo = z * 512, qhi = qlo + 512;
    const int kv = blockIdx.x * 512 + threadIdx.x * 2;

    // preload invl chunk
    if (threadIdx.x < 128)
        ((float4*)ivs)[threadIdx.x] =
            ((const float4*)&invl_g[h * QLEN + qlo])[threadIdx.x];
    __syncthreads();

    const int qstart = (kv >> 7) << 7;                // first q-tile covering kv
    int q = qstart > qlo ? qstart : qlo;
    float cs0 = 0.f, cq0 = 0.f, cs1 = 0.f, cq1 = 0.f;
    const uint32_t* Eb = (const uint32_t*)&Ep[((size_t)h * QLEN) * KVLEN + kv];
    for (; q < qhi; ++q){
        uint32_t u = Eb[(size_t)q * (KVLEN / 2)];
        float iv = ivs[q - qlo];
        __half2 h2 = *(const __half2*)&u;
        float e0 = __half2float(__low2half(h2));
        float e1 = __half2float(__high2half(h2));
        float p0 = e0 * iv, p1 = e1 * iv;
        cs0 += p0; cq0 = fmaf(p0, p0, cq0);
        cs1 += p1; cq1 = fmaf(p1, p1, cq1);
    }
    if (qstart < qhi){
        atomicAdd(&roco[h * QLEN + kv],        cs0);
        atomicAdd(&roco[h * QLEN + kv + 1],    cs1);
        atomicAdd(&roco_sq[h * QLEN + kv],     cq0);
        atomicAdd(&roco_sq[h * QLEN + kv + 1], cq1);
    }
}

extern "C" void kernel_launch(void* const* d_in, const int* in_sizes, int n_in,
                              void* d_out, int out_size)
{
    const float* Qg = (const float*)d_in[0];
    const float* Kg = (const float*)d_in[1];
    const float* Vg = (const float*)d_in[2];
    float* Outg    = (float*)d_out;
    float* roco    = Outg + (size_t)QLEN * HQ * 128;    // 8388608
    float* roco_sq = roco + HQ * QLEN;                  // +65536

    cudaFuncSetAttribute(attn_mma_kernel,
                         cudaFuncAttributeMaxDynamicSharedMemorySize, SM_TOTAL);

    // launch 0: preround; launch 1: zero roco; launch 2: attn; launch 3: colsum
    dim3 gpr(QLEN / 8, HQ, 3);
    preround_kernel<<<gpr, 256>>>(Qg, Kg, Vg);

    const int nz = 2 * HQ * QLEN;
    zero_kernel<<<(nz + 255) / 256, 256>>>(roco, nz);

    dim3 grid1(QLEN / 128, HQ);     // (16, 32)
    attn_mma_kernel<<<grid1, 256, SM_TOTAL>>>(Outg);

    dim3 grid2(KVLEN / 512, HQ, 4); // (4, 32, 4)
    roco_colsum_kernel<<<grid2, 256>>>(roco, roco_sq);
}

// round 11
// speedup vs baseline: 4.0928x; 1.0718x over previous
#include <cuda_runtime.h>
#include <cuda_fp16.h>
#include <cstdint>

#define HQ    32
#define QLEN  2048
#define KVLEN 2048

// rounded, head-major copies of inputs
__device__ float Qp[(size_t)HQ * QLEN * 128];
__device__ float Kp[(size_t)HQ * KVLEN * 128];
__device__ float Vp[(size_t)HQ * KVLEN * 128];
// [h][q][kv] unnormalized exp-scores, fp16
__device__ __half Ep[(size_t)HQ * QLEN * KVLEN];
__device__ float invl_g[HQ * QLEN];

// ---- smem byte offsets ----
#define SM_RED   0
#define SM_Q     2048         // [128][PQ] fp32
#define SM_SLOT0 71680        // K0,K1,V0,V1 slots; also O-stage after the loop
#define SLOT_SZ  34816        // 64*136*4
#define SM_TOTAL 210944

#define PQ 136
#define PK 136
#define PVP 132
#define PSTG 132              // O stage pitch (floats)

#define CPA16(dst, src) \
    asm volatile("cp.async.cg.shared.global [%0], [%1], 16;" :: "r"(dst), "l"(src))
#define CPC() asm volatile("cp.async.commit_group;" ::: "memory")
#define CPWAIT(N) asm volatile("cp.async.wait_group %0;" :: "n"(N) : "memory")

#define MMA_TF32(c, a0, a1, a2, a3, b0, b1) \
    asm volatile("mma.sync.aligned.m16n8k8.row.col.f32.tf32.tf32.f32 " \
        "{%0,%1,%2,%3},{%4,%5,%6,%7},{%8,%9},{%0,%1,%2,%3};" \
        : "+f"((c)[0]), "+f"((c)[1]), "+f"((c)[2]), "+f"((c)[3]) \
        : "r"(a0), "r"(a1), "r"(a2), "r"(a3), "r"(b0), "r"(b1))

#define CVT_RNA(u, f) asm("cvt.rna.tf32.f32 %0, %1;" : "=r"(u) : "f"(f))
#define PACK_F16X2(u, lo, hi) \
    asm("cvt.rn.f16x2.f32 %0, %1, %2;" : "=r"(u) : "f"(hi), "f"(lo))

__device__ __forceinline__ uint32_t smem_u32(const void* p){
    uint32_t a;
    asm("{ .reg .u64 t; cvta.to.shared.u64 t, %1; cvt.u32.u64 %0, t; }" : "=r"(a) : "l"(p));
    return a;
}

// ---- kernel 0a: round Q/K/V to tf32-RNA, transpose to [h][tok][d] ----
__global__ void __launch_bounds__(256, 4)
preround_kernel(const float* __restrict__ Qg, const float* __restrict__ Kg,
                const float* __restrict__ Vg)
{
    const int z = blockIdx.z, h = blockIdx.y;
    const int r = blockIdx.x * 8 + (threadIdx.x >> 5);
    const int c = threadIdx.x & 31;
    const float4* src = (const float4*)(z == 0 ? Qg : (z == 1 ? Kg : Vg));
    uint4* dst = (uint4*)(z == 0 ? Qp : (z == 1 ? Kp : Vp));
    float4 v = src[((size_t)r * HQ + h) * 32 + c];
    uint4 u;
    CVT_RNA(u.x, v.x); CVT_RNA(u.y, v.y); CVT_RNA(u.z, v.z); CVT_RNA(u.w, v.w);
    dst[((size_t)h * QLEN + r) * 32 + c] = u;
}

__global__ void zero_kernel(float* __restrict__ p, int n)
{
    int i = blockIdx.x * blockDim.x + threadIdx.x;
    if (i < n) p[i] = 0.0f;
}

__device__ __forceinline__ void load_k_tile(char* sm, int slot, const float4* gk,
                                            int k0, int h, int tid){
    char* base = sm + SM_SLOT0 + slot * SLOT_SZ;
    for (int i = tid; i < 64 * 32; i += 256){
        int n = i >> 5, c = i & 31;
        CPA16(smem_u32(base + n * (PK * 4) + c * 16),
              &gk[((size_t)h * KVLEN + k0 + n) * 32 + c]);
    }
}
__device__ __forceinline__ void load_v_tile(char* sm, int slot, const float4* gv,
                                            int k0, int h, int tid){
    char* base = sm + SM_SLOT0 + slot * SLOT_SZ;
    for (int i = tid; i < 64 * 32; i += 256){
        int n = i >> 5, c = i & 31;
        CPA16(smem_u32(base + n * (PVP * 4) + c * 16),
              &gv[((size_t)h * KVLEN + k0 + n) * 32 + c]);
    }
}

__global__ void __launch_bounds__(256, 1)
attn_mma_kernel(float* __restrict__ Outg)
{
    extern __shared__ char sm[];
    const int tid = threadIdx.x, w = tid >> 5, lid = tid & 31;
    const int tq = lid >> 2, tr = lid & 3;
    const int h = blockIdx.y;
    const int qi = (gridDim.x - 1) - blockIdx.x;       // heavy tiles first
    const int q0 = qi * 128;
    const int nt = 2 * qi + 2;
    const float scale = 0.08838834764831845f;

    const int wq = w & 3;        // 32-row block
    const int wn = w >> 2;       // QK cols / PV kv-slice: [wn*32, wn*32+32)

    float* red = (float*)(sm + SM_RED);
    float* sQ  = (float*)(sm + SM_Q);

    const float4* gq = (const float4*)Qp;
    const float4* gk = (const float4*)Kp;
    const float4* gv = (const float4*)Vp;

    // ---- prologue: Q + K(0),V(0) ----
    for (int i = tid; i < 128 * 32; i += 256){
        int m = i >> 5, c = i & 31;
        CPA16(smem_u32(sm + SM_Q + m * (PQ * 4) + c * 16),
              &gq[((size_t)h * QLEN + q0 + m) * 32 + c]);
    }
    load_k_tile(sm, 0, gk, 0, h, tid);   // K slots: 0,1
    load_v_tile(sm, 2, gv, 0, h, tid);   // V slots: 2,3
    CPC();

    float acco[2][16][4];                // rows(2 mf) x d(16 nf) x frag; kv-partial (this warp's slice)
    float rsum[4] = {0.f, 0.f, 0.f, 0.f};
#pragma unroll
    for (int mf = 0; mf < 2; ++mf)
#pragma unroll
        for (int nf = 0; nf < 16; ++nf)
#pragma unroll
            for (int x = 0; x < 4; ++x) acco[mf][nf][x] = 0.f;

    for (int t = 0; t < nt; ++t){
        const int cur = t & 1;
        const int k0 = t * 64;

        CPWAIT(0);                // K(t), V(t) landed
        __syncthreads();          // visible to all; prev tile's smem reads done
        if (t + 1 < nt){
            load_k_tile(sm, cur ^ 1, gk, (t + 1) * 64, h, tid);
            load_v_tile(sm, 2 + (cur ^ 1), gv, (t + 1) * 64, h, tid);
            CPC();
        }

        // ================= QK^T (tf32 MMA) =================
        float accs[2][4][4];
#pragma unroll
        for (int mf = 0; mf < 2; ++mf)
#pragma unroll
            for (int nf = 0; nf < 4; ++nf)
#pragma unroll
                for (int x = 0; x < 4; ++x) accs[mf][nf][x] = 0.f;

        const float* Kb = (const float*)(sm + SM_SLOT0 + cur * SLOT_SZ);
#pragma unroll
        for (int j = 0; j < 16; ++j){
            const int col = j * 8 + 2 * tr;      // k-lane c -> global d = 8j + 2(c%4) + c/4
            uint2 a[2][2], b[4];
#pragma unroll
            for (int mf = 0; mf < 2; ++mf)
#pragma unroll
                for (int hf = 0; hf < 2; ++hf)
                    a[mf][hf] = *(const uint2*)(sQ + (wq*32 + mf*16 + hf*8 + tq) * PQ + col);
#pragma unroll
            for (int nf = 0; nf < 4; ++nf)
                b[nf] = *(const uint2*)(Kb + (wn*32 + nf*8 + tq) * PK + col);
#pragma unroll
            for (int mf = 0; mf < 2; ++mf)
#pragma unroll
                for (int nf = 0; nf < 4; ++nf)
                    MMA_TF32(accs[mf][nf],
                             a[mf][0].x, a[mf][1].x, a[mf][0].y, a[mf][1].y,
                             b[nf].x, b[nf].y);
        }

        // ===== epilogue in registers: exp, rsum, E global store =====
        // accs[mf][nf] frag: (tq,2tr),(tq,2tr+1),(tq+8,2tr),(tq+8,2tr+1)
#pragma unroll
        for (int mf = 0; mf < 2; ++mf)
#pragma unroll
            for (int nf = 0; nf < 4; ++nf){
                const int kvb = k0 + wn*32 + nf*8 + 2*tr;
#pragma unroll
                for (int hf = 0; hf < 2; ++hf){
                    const int qrow = q0 + wq*32 + mf*16 + hf*8 + tq;
                    float e0 = (kvb     <= qrow) ? __expf(accs[mf][nf][hf*2    ] * scale) : 0.f;
                    float e1 = (kvb + 1 <= qrow) ? __expf(accs[mf][nf][hf*2 + 1] * scale) : 0.f;
                    rsum[mf*2 + hf] += e0 + e1;
                    accs[mf][nf][hf*2] = e0; accs[mf][nf][hf*2 + 1] = e1;
                    uint32_t pk;
                    PACK_F16X2(pk, e0, e1);
                    *(uint32_t*)&Ep[((size_t)h * QLEN + qrow) * KVLEN + kvb] = pk;
                }
            }

        // ================= PV: QK regs feed A directly =================
        // A-frag for k-step j (kv-lane perm kv=8j+2(c%4)+c/4):
        //   (a0,a1,a2,a3) = (accs[mf][j][0], accs[mf][j][2], accs[mf][j][1], accs[mf][j][3])
        const float* Vb = (const float*)(sm + SM_SLOT0 + (2 + cur) * SLOT_SZ);
#pragma unroll
        for (int j = 0; j < 4; ++j){
            const int kvr = wn*32 + j*8 + 2*tr;   // V rows for b0/b1
            uint32_t b0[16], b1[16];
#pragma unroll
            for (int nf = 0; nf < 16; ++nf){
                const int d = nf*8 + tq;
                b0[nf] = __float_as_uint(Vb[kvr * PVP + d]);
                b1[nf] = __float_as_uint(Vb[(kvr + 1) * PVP + d]);
            }
#pragma unroll
            for (int mf = 0; mf < 2; ++mf){
                const uint32_t a0 = __float_as_uint(accs[mf][j][0]);
                const uint32_t a1 = __float_as_uint(accs[mf][j][2]);
                const uint32_t a2 = __float_as_uint(accs[mf][j][1]);
                const uint32_t a3 = __float_as_uint(accs[mf][j][3]);
#pragma unroll
                for (int nf = 0; nf < 16; ++nf)
                    MMA_TF32(acco[mf][nf], a0, a1, a2, a3, b0[nf], b1[nf]);
            }
        }
    }

    // ---- row sums + stage wn=1 O partials; then combine ----
#pragma unroll
    for (int r = 0; r < 4; ++r){
        rsum[r] += __shfl_xor_sync(0xffffffffu, rsum[r], 1);
        rsum[r] += __shfl_xor_sync(0xffffffffu, rsum[r], 2);
    }
    __syncthreads();             // last tile's smem reads done; slots reusable as stage
    float* stage = (float*)(sm + SM_SLOT0);
    if (tr == 0){
#pragma unroll
        for (int r = 0; r < 4; ++r)
            red[wn * 128 + wq*32 + r*8 + tq] = rsum[r];
    }
    if (wn == 1){
#pragma unroll
        for (int mf = 0; mf < 2; ++mf)
#pragma unroll
            for (int hf = 0; hf < 2; ++hf){
                const int row = wq*32 + mf*16 + hf*8 + tq;
#pragma unroll
                for (int nf = 0; nf < 16; ++nf)
                    *(float2*)&stage[row * PSTG + nf*8 + 2*tr] =
                        make_float2(acco[mf][nf][hf*2], acco[mf][nf][hf*2 + 1]);
            }
    }
    __syncthreads();

    if (wn == 0){
#pragma unroll
        for (int mf = 0; mf < 2; ++mf)
#pragma unroll
            for (int hf = 0; hf < 2; ++hf){
                const int row = wq*32 + mf*16 + hf*8 + tq;
                const float iv = 1.0f / (red[row] + red[128 + row]);
                if (tr == 0 && nullptr == nullptr) { /* keep iv math uniform */ }
                if (tr == 0) invl_g[h * QLEN + q0 + row] = iv;
#pragma unroll
                for (int nf = 0; nf < 16; ++nf){
                    float2 p = *(const float2*)&stage[row * PSTG + nf*8 + 2*tr];
                    *(float2*)&Outg[((size_t)(q0 + row) * HQ + h) * 128 + nf*8 + 2*tr] =
                        make_float2((acco[mf][nf][hf*2]     + p.x) * iv,
                                    (acco[mf][nf][hf*2 + 1] + p.y) * iv);
                }
            }
    }
}

// ---- kernel 2: roco column sums over fp16 E[h][q][kv], q-chunked, MLP=4 ----
__global__ void __launch_bounds__(256, 8)
roco_colsum_kernel(float* __restrict__ roco, float* __restrict__ roco_sq)
{
    __shared__ float ivs[512];
    const int h = blockIdx.y, z = blockIdx.z;
    const int qlo = z * 512, qhi = qlo + 512;
    const int kv = blockIdx.x * 512 + threadIdx.x * 2;

    if (threadIdx.x < 128)
        ((float4*)ivs)[threadIdx.x] =
            ((const float4*)&invl_g[h * QLEN + qlo])[threadIdx.x];
    __syncthreads();

    const int qstart = (kv >> 7) << 7;
    int q = qstart > qlo ? qstart : qlo;      // multiple of 128 or 512 -> mult of 4
    if (q >= qhi) return;

    float cs = 0.f, cq = 0.f;
    const uint32_t* Eb = (const uint32_t*)&Ep[((size_t)h * QLEN) * KVLEN + kv];
    const size_t K2 = KVLEN / 2;
    for (; q + 3 < qhi; q += 4){
        uint32_t u0 = Eb[(size_t)q * K2];
        uint32_t u1 = Eb[(size_t)(q + 1) * K2];
        uint32_t u2 = Eb[(size_t)(q + 2) * K2];
        uint32_t u3 = Eb[(size_t)(q + 3) * K2];
        float4 iv = *(const float4*)&ivs[q - qlo];
        float2 f0 = __half22float2(*(const __half2*)&u0);
        float2 f1 = __half22float2(*(const __half2*)&u1);
        float2 f2 = __half22float2(*(const __half2*)&u2);
        float2 f3 = __half22float2(*(const __half2*)&u3);
        float p0 = f0.x * iv.x, p1 = f0.y * iv.x;
        float p2 = f1.x * iv.y, p3 = f1.y * iv.y;
        float p4 = f2.x * iv.z, p5 = f2.y * iv.z;
        float p6 = f3.x * iv.w, p7 = f3.y * iv.w;
        cs += ((p0 + p2) + (p4 + p6)) + ((p1 + p3) + (p5 + p7));
        cq = fmaf(p0, p0, cq); cq = fmaf(p2, p2, cq);
        cq = fmaf(p4, p4, cq); cq = fmaf(p6, p6, cq);
        cq = fmaf(p1, p1, cq); cq = fmaf(p3, p3, cq);
        cq = fmaf(p5, p5, cq); cq = fmaf(p7, p7, cq);
    }

    // cs/cq currently mix kv and kv+1 columns; recompute split via warp pair trick:
    // (we accumulated both columns into one pair of scalars; redo properly below)
    // -- To keep columns separate, accumulate again with separated sums:
    // NOTE: separated accumulation done inline above would double registers;
    // instead we re-walk using the packed values kept in the loop is not possible.
    // So: the loop above is replaced by a correct two-accumulator version:
    (void)cs; (void)cq;
    float cs0 = 0.f, cq0 = 0.f, cs1 = 0.f, cq1 = 0.f;
    q = qstart > qlo ? qstart : qlo;
    for (; q + 3 < qhi; q += 4){
        uint32_t u0 = Eb[(size_t)q * K2];
        uint32_t u1 = Eb[(size_t)(q + 1) * K2];
        uint32_t u2 = Eb[(size_t)(q + 2) * K2];
        uint32_t u3 = Eb[(size_t)(q + 3) * K2];
        float4 iv = *(const float4*)&ivs[q - qlo];
        float2 f0 = __half22float2(*(const __half2*)&u0);
        float2 f1 = __half22float2(*(const __half2*)&u1);
        float2 f2 = __half22float2(*(const __half2*)&u2);
        float2 f3 = __half22float2(*(const __half2*)&u3);
        float a0 = f0.x * iv.x, b0 = f0.y * iv.x;
        float a1 = f1.x * iv.y, b1 = f1.y * iv.y;
        float a2 = f2.x * iv.z, b2 = f2.y * iv.z;
        float a3 = f3.x * iv.w, b3 = f3.y * iv.w;
        cs0 += (a0 + a1) + (a2 + a3);
        cs1 += (b0 + b1) + (b2 + b3);
        cq0 = fmaf(a0, a0, cq0); cq0 = fmaf(a1, a1, cq0);
        cq0 = fmaf(a2, a2, cq0); cq0 = fmaf(a3, a3, cq0);
        cq1 = fmaf(b0, b0, cq1); cq1 = fmaf(b1, b1, cq1);
        cq1 = fmaf(b2, b2, cq1); cq1 = fmaf(b3, b3, cq1);
    }
    atomicAdd(&roco[h * QLEN + kv],        cs0);
    atomicAdd(&roco[h * QLEN + kv + 1],    cs1);
    atomicAdd(&roco_sq[h * QLEN + kv],     cq0);
    atomicAdd(&roco_sq[h * QLEN + kv + 1], cq1);
}

extern "C" void kernel_launch(void* const* d_in, const int* in_sizes, int n_in,
                              void* d_out, int out_size)
{
    const float* Qg = (const float*)d_in[0];
    const float* Kg = (const float*)d_in[1];
    const float* Vg = (const float*)d_in[2];
    float* Outg    = (float*)d_out;
    float* roco    = Outg + (size_t)QLEN * HQ * 128;    // 8388608
    float* roco_sq = roco + HQ * QLEN;                  // +65536

    cudaFuncSetAttribute(attn_mma_kernel,
                         cudaFuncAttributeMaxDynamicSharedMemorySize, SM_TOTAL);

    dim3 gpr(QLEN / 8, HQ, 3);
    preround_kernel<<<gpr, 256>>>(Qg, Kg, Vg);

    const int nz = 2 * HQ * QLEN;
    zero_kernel<<<(nz + 255) / 256, 256>>>(roco, nz);

    dim3 grid1(QLEN / 128, HQ);     // (16, 32)
    attn_mma_kernel<<<grid1, 256, SM_TOTAL>>>(Outg);

    dim3 grid2(KVLEN / 512, HQ, 4); // (4, 32, 4)
    roco_colsum_kernel<<<grid2, 256>>>(roco, roco_sq);
}

// round 12
// speedup vs baseline: 4.1526x; 1.0146x over previous
#include <cuda_runtime.h>
#include <cuda_fp16.h>
#include <cstdint>

#define HQ    32
#define QLEN  2048
#define KVLEN 2048

// rounded, head-major copies of inputs
__device__ float Qp[(size_t)HQ * QLEN * 128];
__device__ float Kp[(size_t)HQ * KVLEN * 128];
__device__ float Vp[(size_t)HQ * KVLEN * 128];
// [h][q][kv] unnormalized exp-scores, fp16
__device__ __half Ep[(size_t)HQ * QLEN * KVLEN];
__device__ float invl_g[HQ * QLEN];

// ---- smem byte offsets ----
#define SM_RED   0
#define SM_Q     2048         // [128][PQ] fp32
#define SM_SLOT0 71680        // K0,K1,V0,V1 slots; also O-stage after the loop
#define SLOT_SZ  34816        // 64*136*4
#define SM_TOTAL 210944

#define PQ 136
#define PK 136
#define PVP 132
#define PSTG 132              // O stage pitch (floats)

#define NT 512

#define CPA16(dst, src) \
    asm volatile("cp.async.cg.shared.global [%0], [%1], 16;" :: "r"(dst), "l"(src))
#define CPC() asm volatile("cp.async.commit_group;" ::: "memory")
#define CPWAIT(N) asm volatile("cp.async.wait_group %0;" :: "n"(N) : "memory")

#define MMA_TF32(c, a0, a1, a2, a3, b0, b1) \
    asm volatile("mma.sync.aligned.m16n8k8.row.col.f32.tf32.tf32.f32 " \
        "{%0,%1,%2,%3},{%4,%5,%6,%7},{%8,%9},{%0,%1,%2,%3};" \
        : "+f"((c)[0]), "+f"((c)[1]), "+f"((c)[2]), "+f"((c)[3]) \
        : "r"(a0), "r"(a1), "r"(a2), "r"(a3), "r"(b0), "r"(b1))

#define CVT_RNA(u, f) asm("cvt.rna.tf32.f32 %0, %1;" : "=r"(u) : "f"(f))
#define PACK_F16X2(u, lo, hi) \
    asm("cvt.rn.f16x2.f32 %0, %1, %2;" : "=r"(u) : "f"(hi), "f"(lo))

__device__ __forceinline__ uint32_t smem_u32(const void* p){
    uint32_t a;
    asm("{ .reg .u64 t; cvta.to.shared.u64 t, %1; cvt.u32.u64 %0, t; }" : "=r"(a) : "l"(p));
    return a;
}

// ---- kernel 0a: round Q/K/V to tf32-RNA, transpose to [h][tok][d] ----
__global__ void __launch_bounds__(256, 4)
preround_kernel(const float* __restrict__ Qg, const float* __restrict__ Kg,
                const float* __restrict__ Vg)
{
    const int z = blockIdx.z, h = blockIdx.y;
    const int r = blockIdx.x * 8 + (threadIdx.x >> 5);
    const int c = threadIdx.x & 31;
    const float4* src = (const float4*)(z == 0 ? Qg : (z == 1 ? Kg : Vg));
    uint4* dst = (uint4*)(z == 0 ? Qp : (z == 1 ? Kp : Vp));
    float4 v = src[((size_t)r * HQ + h) * 32 + c];
    uint4 u;
    CVT_RNA(u.x, v.x); CVT_RNA(u.y, v.y); CVT_RNA(u.z, v.z); CVT_RNA(u.w, v.w);
    dst[((size_t)h * QLEN + r) * 32 + c] = u;
}

__global__ void zero_kernel(float* __restrict__ p, int n)
{
    int i = blockIdx.x * blockDim.x + threadIdx.x;
    if (i < n) p[i] = 0.0f;
}

__device__ __forceinline__ void load_k_tile(char* sm, int slot, const float4* gk,
                                            int k0, int h, int tid){
    char* base = sm + SM_SLOT0 + slot * SLOT_SZ;
    for (int i = tid; i < 64 * 32; i += NT){
        int n = i >> 5, c = i & 31;
        CPA16(smem_u32(base + n * (PK * 4) + c * 16),
              &gk[((size_t)h * KVLEN + k0 + n) * 32 + c]);
    }
}
__device__ __forceinline__ void load_v_tile(char* sm, int slot, const float4* gv,
                                            int k0, int h, int tid){
    char* base = sm + SM_SLOT0 + slot * SLOT_SZ;
    for (int i = tid; i < 64 * 32; i += NT){
        int n = i >> 5, c = i & 31;
        CPA16(smem_u32(base + n * (PVP * 4) + c * 16),
              &gv[((size_t)h * KVLEN + k0 + n) * 32 + c]);
    }
}

__global__ void __launch_bounds__(NT, 1)
attn_mma_kernel(float* __restrict__ Outg)
{
    extern __shared__ char sm[];
    const int tid = threadIdx.x, w = tid >> 5, lid = tid & 31;
    const int tq = lid >> 2, tr = lid & 3;
    const int h = blockIdx.y;
    const int qi = (gridDim.x - 1) - blockIdx.x;       // heavy tiles first
    const int q0 = qi * 128;
    const int nt = 2 * qi + 2;
    const float scale = 0.08838834764831845f;

    const int wq = w & 7;        // 16-row block
    const int wn = w >> 3;       // QK cols / PV kv-slice: [wn*32, wn*32+32)

    float* red = (float*)(sm + SM_RED);
    float* sQ  = (float*)(sm + SM_Q);

    const float4* gq = (const float4*)Qp;
    const float4* gk = (const float4*)Kp;
    const float4* gv = (const float4*)Vp;

    // ---- prologue: Q + K(0),V(0) ----
    for (int i = tid; i < 128 * 32; i += NT){
        int m = i >> 5, c = i & 31;
        CPA16(smem_u32(sm + SM_Q + m * (PQ * 4) + c * 16),
              &gq[((size_t)h * QLEN + q0 + m) * 32 + c]);
    }
    load_k_tile(sm, 0, gk, 0, h, tid);   // K slots: 0,1
    load_v_tile(sm, 2, gv, 0, h, tid);   // V slots: 2,3
    CPC();

    float acco[16][4];                   // d(16 nf) x frag; kv-partial over this warp's slice
    float rsum[2] = {0.f, 0.f};
#pragma unroll
    for (int nf = 0; nf < 16; ++nf)
#pragma unroll
        for (int x = 0; x < 4; ++x) acco[nf][x] = 0.f;

    for (int t = 0; t < nt; ++t){
        const int cur = t & 1;
        const int k0 = t * 64;

        CPWAIT(0);                // K(t), V(t) landed
        __syncthreads();          // visible to all; prev tile's smem reads done
        if (t + 1 < nt){
            load_k_tile(sm, cur ^ 1, gk, (t + 1) * 64, h, tid);
            load_v_tile(sm, 2 + (cur ^ 1), gv, (t + 1) * 64, h, tid);
            CPC();
        }

        // ================= QK^T (tf32 MMA) =================
        float accs[4][4];
#pragma unroll
        for (int nf = 0; nf < 4; ++nf)
#pragma unroll
            for (int x = 0; x < 4; ++x) accs[nf][x] = 0.f;

        const float* Kb = (const float*)(sm + SM_SLOT0 + cur * SLOT_SZ);
#pragma unroll
        for (int j = 0; j < 16; ++j){
            const int col = j * 8 + 2 * tr;      // k-lane c -> global d = 8j + 2(c%4) + c/4
            uint2 a[2], b[4];
#pragma unroll
            for (int hf = 0; hf < 2; ++hf)
                a[hf] = *(const uint2*)(sQ + (wq*16 + hf*8 + tq) * PQ + col);
#pragma unroll
            for (int nf = 0; nf < 4; ++nf)
                b[nf] = *(const uint2*)(Kb + (wn*32 + nf*8 + tq) * PK + col);
#pragma unroll
            for (int nf = 0; nf < 4; ++nf)
                MMA_TF32(accs[nf], a[0].x, a[1].x, a[0].y, a[1].y, b[nf].x, b[nf].y);
        }

        // ===== epilogue in registers: exp, rsum, E global store =====
#pragma unroll
        for (int nf = 0; nf < 4; ++nf){
            const int kvb = k0 + wn*32 + nf*8 + 2*tr;
#pragma unroll
            for (int hf = 0; hf < 2; ++hf){
                const int qrow = q0 + wq*16 + hf*8 + tq;
                float e0 = (kvb     <= qrow) ? __expf(accs[nf][hf*2    ] * scale) : 0.f;
                float e1 = (kvb + 1 <= qrow) ? __expf(accs[nf][hf*2 + 1] * scale) : 0.f;
                rsum[hf] += e0 + e1;
                accs[nf][hf*2] = e0; accs[nf][hf*2 + 1] = e1;
                uint32_t pk;
                PACK_F16X2(pk, e0, e1);
                *(uint32_t*)&Ep[((size_t)h * QLEN + qrow) * KVLEN + kvb] = pk;
            }
        }

        // ================= PV: QK regs feed A directly =================
        const float* Vb = (const float*)(sm + SM_SLOT0 + (2 + cur) * SLOT_SZ);
#pragma unroll
        for (int j = 0; j < 4; ++j){
            const int kvr = wn*32 + j*8 + 2*tr;
            const uint32_t a0 = __float_as_uint(accs[j][0]);
            const uint32_t a1 = __float_as_uint(accs[j][2]);
            const uint32_t a2 = __float_as_uint(accs[j][1]);
            const uint32_t a3 = __float_as_uint(accs[j][3]);
#pragma unroll
            for (int half = 0; half < 2; ++half){
                uint32_t b0[8], b1[8];
#pragma unroll
                for (int f = 0; f < 8; ++f){
                    const int d = (half*8 + f)*8 + tq;
                    b0[f] = __float_as_uint(Vb[kvr * PVP + d]);
                    b1[f] = __float_as_uint(Vb[(kvr + 1) * PVP + d]);
                }
#pragma unroll
                for (int f = 0; f < 8; ++f)
                    MMA_TF32(acco[half*8 + f], a0, a1, a2, a3, b0[f], b1[f]);
            }
        }
    }

    // ---- row sums (reduce over tr lanes) ----
#pragma unroll
    for (int r = 0; r < 2; ++r){
        rsum[r] += __shfl_xor_sync(0xffffffffu, rsum[r], 1);
        rsum[r] += __shfl_xor_sync(0xffffffffu, rsum[r], 2);
    }
    __syncthreads();             // last tile smem reads done; slots reusable as stage
    float* stage = (float*)(sm + SM_SLOT0);
    if (tr == 0){
#pragma unroll
        for (int r = 0; r < 2; ++r)
            red[wn * 128 + wq*16 + r*8 + tq] = rsum[r];
    }
    if (wn == 1){
#pragma unroll
        for (int hf = 0; hf < 2; ++hf){
            const int row = wq*16 + hf*8 + tq;
#pragma unroll
            for (int nf = 0; nf < 16; ++nf)
                *(float2*)&stage[row * PSTG + nf*8 + 2*tr] =
                    make_float2(acco[nf][hf*2], acco[nf][hf*2 + 1]);
        }
    }
    __syncthreads();

    if (wn == 0){
#pragma unroll
        for (int hf = 0; hf < 2; ++hf){
            const int row = wq*16 + hf*8 + tq;
            const float iv = 1.0f / (red[row] + red[128 + row]);
            if (tr == 0) invl_g[h * QLEN + q0 + row] = iv;
#pragma unroll
            for (int nf = 0; nf < 16; ++nf){
                float2 p = *(const float2*)&stage[row * PSTG + nf*8 + 2*tr];
                *(float2*)&Outg[((size_t)(q0 + row) * HQ + h) * 128 + nf*8 + 2*tr] =
                    make_float2((acco[nf][hf*2]     + p.x) * iv,
                                (acco[nf][hf*2 + 1] + p.y) * iv);
            }
        }
    }
}

// ---- kernel 2: roco column sums over fp16 E[h][q][kv], q-chunked, MLP=4 ----
__global__ void __launch_bounds__(256, 8)
roco_colsum_kernel(float* __restrict__ roco, float* __restrict__ roco_sq)
{
    __shared__ float ivs[256];
    const int h = blockIdx.y, z = blockIdx.z;
    const int qlo = z * 256, qhi = qlo + 256;
    const int kv = blockIdx.x * 512 + threadIdx.x * 2;

    if (threadIdx.x < 64)
        ((float4*)ivs)[threadIdx.x] =
            ((const float4*)&invl_g[h * QLEN + qlo])[threadIdx.x];
    __syncthreads();

    const int qstart = (kv >> 7) << 7;        // first q-tile covering kv
    if (qstart >= qhi) return;                 // chunk fully masked
    int q = qstart > qlo ? qstart : qlo;       // multiple of 128/256

    float cs0 = 0.f, cq0 = 0.f, cs1 = 0.f, cq1 = 0.f;
    const uint32_t* Eb = (const uint32_t*)&Ep[((size_t)h * QLEN) * KVLEN + kv];
    const size_t K2 = KVLEN / 2;
    for (; q + 3 < qhi; q += 4){
        uint32_t u0 = Eb[(size_t)q * K2];
        uint32_t u1 = Eb[(size_t)(q + 1) * K2];
        uint32_t u2 = Eb[(size_t)(q + 2) * K2];
        uint32_t u3 = Eb[(size_t)(q + 3) * K2];
        float4 iv = *(const float4*)&ivs[q - qlo];
        float2 f0 = __half22float2(*(const __half2*)&u0);
        float2 f1 = __half22float2(*(const __half2*)&u1);
        float2 f2 = __half22float2(*(const __half2*)&u2);
        float2 f3 = __half22float2(*(const __half2*)&u3);
        float a0 = f0.x * iv.x, b0 = f0.y * iv.x;
        float a1 = f1.x * iv.y, b1 = f1.y * iv.y;
        float a2 = f2.x * iv.z, b2 = f2.y * iv.z;
        float a3 = f3.x * iv.w, b3 = f3.y * iv.w;
        cs0 += (a0 + a1) + (a2 + a3);
        cs1 += (b0 + b1) + (b2 + b3);
        cq0 = fmaf(a0, a0, cq0); cq0 = fmaf(a1, a1, cq0);
        cq0 = fmaf(a2, a2, cq0); cq0 = fmaf(a3, a3, cq0);
        cq1 = fmaf(b0, b0, cq1); cq1 = fmaf(b1, b1, cq1);
        cq1 = fmaf(b2, b2, cq1); cq1 = fmaf(b3, b3, cq1);
    }
    atomicAdd(&roco[h * QLEN + kv],        cs0);
    atomicAdd(&roco[h * QLEN + kv + 1],    cs1);
    atomicAdd(&roco_sq[h * QLEN + kv],     cq0);
    atomicAdd(&roco_sq[h * QLEN + kv + 1], cq1);
}

extern "C" void kernel_launch(void* const* d_in, const int* in_sizes, int n_in,
                              void* d_out, int out_size)
{
    const float* Qg = (const float*)d_in[0];
    const float* Kg = (const float*)d_in[1];
    const float* Vg = (const float*)d_in[2];
    float* Outg    = (float*)d_out;
    float* roco    = Outg + (size_t)QLEN * HQ * 128;    // 8388608
    float* roco_sq = roco + HQ * QLEN;                  // +65536

    cudaFuncSetAttribute(attn_mma_kernel,
                         cudaFuncAttributeMaxDynamicSharedMemorySize, SM_TOTAL);

    dim3 gpr(QLEN / 8, HQ, 3);
    preround_kernel<<<gpr, 256>>>(Qg, Kg, Vg);

    const int nz = 2 * HQ * QLEN;
    zero_kernel<<<(nz + 255) / 256, 256>>>(roco, nz);

    dim3 grid1(QLEN / 128, HQ);     // (16, 32)
    attn_mma_kernel<<<grid1, NT, SM_TOTAL>>>(Outg);

    dim3 grid2(KVLEN / 512, HQ, 8); // (4, 32, 8)
    roco_colsum_kernel<<<grid2, 256>>>(roco, roco_sq);
}

// round 14
// speedup vs baseline: 4.1694x; 1.0040x over previous
#include <cuda_runtime.h>
#include <cuda_fp16.h>
#include <cstdint>

#define HQ    32
#define QLEN  2048
#define KVLEN 2048

// rounded, head-major copies
__device__ float Qp[(size_t)HQ * QLEN * 128];
__device__ float Kp[(size_t)HQ * KVLEN * 128];
__device__ float Vtg[(size_t)HQ * 128 * KVLEN];     // [h][d][kv], tf32-RNA
// [h][q][kv] unnormalized exp-scores, fp16
__device__ __half Ep[(size_t)HQ * QLEN * KVLEN];
__device__ float invl_g[HQ * QLEN];

#define CPA16(dst, src) \
    asm volatile("cp.async.cg.shared.global [%0], [%1], 16;" :: "r"(dst), "l"(src))
#define CPC() asm volatile("cp.async.commit_group;" ::: "memory")
#define CPWAIT(N) asm volatile("cp.async.wait_group %0;" :: "n"(N) : "memory")

#define MMA_TF32(c, a0, a1, a2, a3, b0, b1) \
    asm volatile("mma.sync.aligned.m16n8k8.row.col.f32.tf32.tf32.f32 " \
        "{%0,%1,%2,%3},{%4,%5,%6,%7},{%8,%9},{%0,%1,%2,%3};" \
        : "+f"((c)[0]), "+f"((c)[1]), "+f"((c)[2]), "+f"((c)[3]) \
        : "r"(a0), "r"(a1), "r"(a2), "r"(a3), "r"(b0), "r"(b1))

#define CVT_RNA(u, f) asm("cvt.rna.tf32.f32 %0, %1;" : "=r"(u) : "f"(f))
#define PACK_F16X2(u, lo, hi) \
    asm("cvt.rn.f16x2.f32 %0, %1, %2;" : "=r"(u) : "f"(hi), "f"(lo))

__device__ __forceinline__ uint32_t smem_u32(const void* p){
    uint32_t a;
    asm("{ .reg .u64 t; cvta.to.shared.u64 t, %1; cvt.u32.u64 %0, t; }" : "=r"(a) : "l"(p));
    return a;
}

// ---- kernel 0a: round Q/K to tf32-RNA, transpose to [h][tok][d] ----
__global__ void __launch_bounds__(256, 4)
preround_kernel(const float* __restrict__ Qg, const float* __restrict__ Kg)
{
    const int z = blockIdx.z, h = blockIdx.y;
    const int r = blockIdx.x * 8 + (threadIdx.x >> 5);
    const int c = threadIdx.x & 31;
    const float4* src = (const float4*)(z == 0 ? Qg : Kg);
    uint4* dst = (uint4*)(z == 0 ? Qp : Kp);
    float4 v = src[((size_t)r * HQ + h) * 32 + c];
    uint4 u;
    CVT_RNA(u.x, v.x); CVT_RNA(u.y, v.y); CVT_RNA(u.z, v.z); CVT_RNA(u.w, v.w);
    dst[((size_t)h * QLEN + r) * 32 + c] = u;
}

// ---- kernel 0b: V -> Vtg[h][d][kv] with RNA rounding (smem tile transpose) ----
__global__ void __launch_bounds__(256, 4)
vtrans_kernel(const float* __restrict__ Vg)
{
    __shared__ float t[32][33];
    const int h = blockIdx.z;
    const int r0 = blockIdx.x * 32, d0 = blockIdx.y * 32;
    const int x = threadIdx.x & 31, y = threadIdx.x >> 5;
#pragma unroll
    for (int k = 0; k < 4; k++){
        int r = r0 + y + k * 8;
        float v = Vg[((size_t)r * HQ + h) * 128 + d0 + x];
        uint32_t u; CVT_RNA(u, v);
        t[y + k * 8][x] = __uint_as_float(u);
    }
    __syncthreads();
#pragma unroll
    for (int k = 0; k < 4; k++){
        int d = d0 + y + k * 8;
        Vtg[((size_t)h * 128 + d) * KVLEN + r0 + x] = t[x][y + k * 8];
    }
}

__global__ void zero_kernel(float* __restrict__ p, int n)
{
    int i = blockIdx.x * blockDim.x + threadIdx.x;
    if (i < n) p[i] = 0.0f;
}

// =================== QK kernel: S=QK^T, exp, E fp16, invl ===================
#define QK_NT   512
#define PQ      136
#define PK      136
#define QK_RED  0          // 4*128 floats
#define QK_Q    2048       // 128*136*4 = 69632
#define QK_K0   71680      // 2 slots of 64*136*4
#define QK_SLOT 34816
#define QK_TOTAL 141312

__device__ __forceinline__ void qk_load_k(char* sm, int slot, const float4* gk,
                                          int k0, int h, int tid){
    char* base = sm + QK_K0 + slot * QK_SLOT;
    for (int i = tid; i < 64 * 32; i += QK_NT){
        int n = i >> 5, c = i & 31;
        CPA16(smem_u32(base + n * (PK * 4) + c * 16),
              &gk[((size_t)h * KVLEN + k0 + n) * 32 + c]);
    }
}

__global__ void __launch_bounds__(QK_NT, 1)
qk_kernel()
{
    extern __shared__ char sm[];
    const int tid = threadIdx.x, w = tid >> 5, lid = tid & 31;
    const int tq = lid >> 2, tr = lid & 3;
    const int h = blockIdx.y;
    const int qi = (gridDim.x - 1) - blockIdx.x;       // heavy tiles first
    const int q0 = qi * 128;
    const int nt = 2 * qi + 2;
    const float scale = 0.08838834764831845f;

    const int wq = w & 3;      // 32-row block
    const int wn = w >> 2;     // 16-col kv slice

    float* sQ = (float*)(sm + QK_Q);
    const float4* gq = (const float4*)Qp;
    const float4* gk = (const float4*)Kp;

    for (int i = tid; i < 128 * 32; i += QK_NT){
        int m = i >> 5, c = i & 31;
        CPA16(smem_u32(sm + QK_Q + m * (PQ * 4) + c * 16),
              &gq[((size_t)h * QLEN + q0 + m) * 32 + c]);
    }
    qk_load_k(sm, 0, gk, 0, h, tid);
    CPC();

    float rsum[4] = {0.f, 0.f, 0.f, 0.f};

    for (int t = 0; t < nt; ++t){
        const int cur = t & 1;
        const int k0 = t * 64;

        CPWAIT(0);
        __syncthreads();
        if (t + 1 < nt){ qk_load_k(sm, cur ^ 1, gk, (t + 1) * 64, h, tid); CPC(); }

        float accs[2][2][4];
#pragma unroll
        for (int mf = 0; mf < 2; ++mf)
#pragma unroll
            for (int nf = 0; nf < 2; ++nf)
#pragma unroll
                for (int x = 0; x < 4; ++x) accs[mf][nf][x] = 0.f;

        const float* Kb = (const float*)(sm + QK_K0 + cur * QK_SLOT);
#pragma unroll
        for (int j = 0; j < 16; ++j){
            const int col = j * 8 + 2 * tr;     // k-lane c -> d = 8j + 2(c%4) + c/4
            uint2 a[2][2], b[2];
#pragma unroll
            for (int mf = 0; mf < 2; ++mf){
                a[mf][0] = *(const uint2*)(sQ + (wq*32 + mf*16 + tq) * PQ + col);
                a[mf][1] = *(const uint2*)(sQ + (wq*32 + mf*16 + 8 + tq) * PQ + col);
            }
#pragma unroll
            for (int nf = 0; nf < 2; ++nf)
                b[nf] = *(const uint2*)(Kb + (wn*16 + nf*8 + tq) * PK + col);
#pragma unroll
            for (int mf = 0; mf < 2; ++mf)
#pragma unroll
                for (int nf = 0; nf < 2; ++nf)
                    MMA_TF32(accs[mf][nf],
                             a[mf][0].x, a[mf][1].x, a[mf][0].y, a[mf][1].y,
                             b[nf].x, b[nf].y);
        }

        // epilogue: exp, rsum, E fp16 store
#pragma unroll
        for (int mf = 0; mf < 2; ++mf)
#pragma unroll
            for (int nf = 0; nf < 2; ++nf){
                const int kvb = k0 + wn*16 + nf*8 + 2*tr;
#pragma unroll
                for (int hf = 0; hf < 2; ++hf){
                    const int qrow = q0 + wq*32 + mf*16 + hf*8 + tq;
                    float e0 = (kvb     <= qrow) ? __expf(accs[mf][nf][hf*2    ] * scale) : 0.f;
                    float e1 = (kvb + 1 <= qrow) ? __expf(accs[mf][nf][hf*2 + 1] * scale) : 0.f;
                    rsum[mf*2 + hf] += e0 + e1;
                    uint32_t pk;
                    PACK_F16X2(pk, e0, e1);
                    *(uint32_t*)&Ep[((size_t)h * QLEN + qrow) * KVLEN + kvb] = pk;
                }
            }
    }

    // reduce row sums: tr lanes, then 4 wn groups via smem
#pragma unroll
    for (int r = 0; r < 4; ++r){
        rsum[r] += __shfl_xor_sync(0xffffffffu, rsum[r], 1);
        rsum[r] += __shfl_xor_sync(0xffffffffu, rsum[r], 2);
    }
    float* red = (float*)(sm + QK_RED);
    if (tr == 0){
#pragma unroll
        for (int r = 0; r < 4; ++r){
            const int row = wq*32 + (r >> 1)*16 + (r & 1)*8 + tq;
            red[wn * 128 + row] = rsum[r];
        }
    }
    __syncthreads();
    if (tid < 128){
        float s = (red[tid] + red[128 + tid]) + (red[256 + tid] + red[384 + tid]);
        invl_g[h * QLEN + q0 + tid] = 1.0f / s;
    }
}

// =================== PV GEMM: O = (E fp16 -> tf32) * Vt, scaled by invl ===================
#define PV_NT   256
#define PE2     72          // halves pitch
#define PVT     72          // floats pitch
#define PV_E0   0           // 2 x 128*72*2 = 18432
#define PV_EB   18432
#define PV_V0   36864       // 2 x 128*72*4 = 36864
#define PV_VB   36864
#define PV_TOTAL 110592

__device__ __forceinline__ void pv_load(char* sm, int buf, int k0, int h, int q0, int tid){
    char* eb = sm + PV_E0 + buf * PV_EB;
    for (int i = tid; i < 128 * 8; i += PV_NT){
        int r = i >> 3, c = i & 7;
        CPA16(smem_u32(eb + r * (PE2 * 2) + c * 16),
              &Ep[((size_t)h * QLEN + q0 + r) * KVLEN + k0 + c * 8]);
    }
    char* vb = sm + PV_V0 + buf * PV_VB;
    for (int i = tid; i < 128 * 16; i += PV_NT){
        int d = i >> 4, c = i & 15;
        CPA16(smem_u32(vb + d * (PVT * 4) + c * 16),
              &Vtg[((size_t)h * 128 + d) * KVLEN + k0 + c * 4]);
    }
}

__global__ void __launch_bounds__(PV_NT, 2)
pv_kernel(float* __restrict__ Outg)
{
    extern __shared__ char sm[];
    const int tid = threadIdx.x, w = tid >> 5, lid = tid & 31;
    const int tq = lid >> 2, tr = lid & 3;
    const int h = blockIdx.y;
    const int qi = (gridDim.x - 1) - blockIdx.x;
    const int q0 = qi * 128;
    const int nt = 2 * qi + 2;

    const int wq = w & 3;      // 32-row block
    const int wd = w >> 2;     // 64-d block

    pv_load(sm, 0, 0, h, q0, tid);
    CPC();

    float acco[2][8][4];
#pragma unroll
    for (int mf = 0; mf < 2; ++mf)
#pragma unroll
        for (int nf = 0; nf < 8; ++nf)
#pragma unroll
            for (int x = 0; x < 4; ++x) acco[mf][nf][x] = 0.f;

    for (int t = 0; t < nt; ++t){
        const int cur = t & 1;
        CPWAIT(0);
        __syncthreads();
        if (t + 1 < nt){ pv_load(sm, cur ^ 1, (t + 1) * 64, h, q0, tid); CPC(); }

        const __half* sE = (const __half*)(sm + PV_E0 + cur * PV_EB);
        const float*  sV = (const float*)(sm + PV_V0 + cur * PV_VB);
#pragma unroll
        for (int j = 0; j < 8; ++j){
            const int kc = j * 8 + 2 * tr;      // k-lane perm: kv = 8j + 2(c%4) + c/4
            uint32_t a0[2], a1[2], a2[2], a3[2];
#pragma unroll
            for (int mf = 0; mf < 2; ++mf){
                __half2 lo = *(const __half2*)(sE + (wq*32 + mf*16 + tq) * PE2 + kc);
                __half2 hi = *(const __half2*)(sE + (wq*32 + mf*16 + 8 + tq) * PE2 + kc);
                float2 flo = __half22float2(lo);
                float2 fhi = __half22float2(hi);
                a0[mf] = __float_as_uint(flo.x);
                a1[mf] = __float_as_uint(fhi.x);
                a2[mf] = __float_as_uint(flo.y);
                a3[mf] = __float_as_uint(fhi.y);
            }
            uint2 b[8];
#pragma unroll
            for (int nf = 0; nf < 8; ++nf)
                b[nf] = *(const uint2*)(sV + (wd*64 + nf*8 + tq) * PVT + kc);
#pragma unroll
            for (int mf = 0; mf < 2; ++mf)
#pragma unroll
                for (int nf = 0; nf < 8; ++nf)
                    MMA_TF32(acco[mf][nf], a0[mf], a1[mf], a2[mf], a3[mf],
                             b[nf].x, b[nf].y);
        }
    }

    // writeout with invl scaling
#pragma unroll
    for (int mf = 0; mf < 2; ++mf)
#pragma unroll
        for (int hf = 0; hf < 2; ++hf){
            const int row = wq*32 + mf*16 + hf*8 + tq;
            const float iv = invl_g[h * QLEN + q0 + row];
#pragma unroll
            for (int nf = 0; nf < 8; ++nf){
                const int d = wd*64 + nf*8 + 2*tr;
                *(float2*)&Outg[((size_t)(q0 + row) * HQ + h) * 128 + d] =
                    make_float2(acco[mf][nf][hf*2] * iv, acco[mf][nf][hf*2 + 1] * iv);
            }
        }
}

// ---- colsum: roco over fp16 E[h][q][kv], q-chunked, MLP=4 ----
__global__ void __launch_bounds__(256, 8)
roco_colsum_kernel(float* __restrict__ roco, float* __restrict__ roco_sq)
{
    __shared__ float ivs[256];
    const int h = blockIdx.y, z = blockIdx.z;
    const int qlo = z * 256, qhi = qlo + 256;
    const int kv = blockIdx.x * 512 + threadIdx.x * 2;

    if (threadIdx.x < 64)
        ((float4*)ivs)[threadIdx.x] =
            ((const float4*)&invl_g[h * QLEN + qlo])[threadIdx.x];
    __syncthreads();

    const int qstart = (kv >> 7) << 7;
    if (qstart >= qhi) return;
    int q = qstart > qlo ? qstart : qlo;

    float cs0 = 0.f, cq0 = 0.f, cs1 = 0.f, cq1 = 0.f;
    const uint32_t* Eb = (const uint32_t*)&Ep[((size_t)h * QLEN) * KVLEN + kv];
    const size_t K2 = KVLEN / 2;
    for (; q + 3 < qhi; q += 4){
        uint32_t u0 = Eb[(size_t)q * K2];
        uint32_t u1 = Eb[(size_t)(q + 1) * K2];
        uint32_t u2 = Eb[(size_t)(q + 2) * K2];
        uint32_t u3 = Eb[(size_t)(q + 3) * K2];
        float4 iv = *(const float4*)&ivs[q - qlo];
        float2 f0 = __half22float2(*(const __half2*)&u0);
        float2 f1 = __half22float2(*(const __half2*)&u1);
        float2 f2 = __half22float2(*(const __half2*)&u2);
        float2 f3 = __half22float2(*(const __half2*)&u3);
        float a0 = f0.x * iv.x, b0 = f0.y * iv.x;
        float a1 = f1.x * iv.y, b1 = f1.y * iv.y;
        float a2 = f2.x * iv.z, b2 = f2.y * iv.z;
        float a3 = f3.x * iv.w, b3 = f3.y * iv.w;
        cs0 += (a0 + a1) + (a2 + a3);
        cs1 += (b0 + b1) + (b2 + b3);
        cq0 = fmaf(a0, a0, cq0); cq0 = fmaf(a1, a1, cq0);
        cq0 = fmaf(a2, a2, cq0); cq0 = fmaf(a3, a3, cq0);
        cq1 = fmaf(b0, b0, cq1); cq1 = fmaf(b1, b1, cq1);
        cq1 = fmaf(b2, b2, cq1); cq1 = fmaf(b3, b3, cq1);
    }
    atomicAdd(&roco[h * QLEN + kv],        cs0);
    atomicAdd(&roco[h * QLEN + kv + 1],    cs1);
    atomicAdd(&roco_sq[h * QLEN + kv],     cq0);
    atomicAdd(&roco_sq[h * QLEN + kv + 1], cq1);
}

extern "C" void kernel_launch(void* const* d_in, const int* in_sizes, int n_in,
                              void* d_out, int out_size)
{
    const float* Qg = (const float*)d_in[0];
    const float* Kg = (const float*)d_in[1];
    const float* Vg = (const float*)d_in[2];
    float* Outg    = (float*)d_out;
    float* roco    = Outg + (size_t)QLEN * HQ * 128;    // 8388608
    float* roco_sq = roco + HQ * QLEN;                  // +65536

    cudaFuncSetAttribute(qk_kernel,
                         cudaFuncAttributeMaxDynamicSharedMemorySize, QK_TOTAL);
    cudaFuncSetAttribute(pv_kernel,
                         cudaFuncAttributeMaxDynamicSharedMemorySize, PV_TOTAL);

    dim3 gpr(QLEN / 8, HQ, 2);
    preround_kernel<<<gpr, 256>>>(Qg, Kg);

    dim3 gvt(KVLEN / 32, 128 / 32, HQ);
    vtrans_kernel<<<gvt, 256>>>(Vg);

    const int nz = 2 * HQ * QLEN;
    zero_kernel<<<(nz + 255) / 256, 256>>>(roco, nz);

    dim3 g1(QLEN / 128, HQ);        // (16, 32)
    qk_kernel<<<g1, QK_NT, QK_TOTAL>>>();

    pv_kernel<<<g1, PV_NT, PV_TOTAL>>>(Outg);

    dim3 g2(KVLEN / 512, HQ, 8);    // (4, 32, 8)
    roco_colsum_kernel<<<g2, 256>>>(roco, roco_sq);
}

// round 15
// speedup vs baseline: 4.1733x; 1.0009x over previous
#include <cuda_runtime.h>
#include <cuda_fp16.h>
#include <cstdint>

#define HQ    32
#define QLEN  2048
#define KVLEN 2048

// rounded, head-major copies
__device__ float Qp[(size_t)HQ * QLEN * 128];
__device__ float Kp[(size_t)HQ * KVLEN * 128];
__device__ float Vtg[(size_t)HQ * 128 * KVLEN];     // [h][d][kv], tf32-RNA
// [h][q][kv] unnormalized exp-scores, fp16
__device__ __half Ep[(size_t)HQ * QLEN * KVLEN];
__device__ float invl_g[HQ * QLEN];

#define CPA16(dst, src) \
    asm volatile("cp.async.cg.shared.global [%0], [%1], 16;" :: "r"(dst), "l"(src))
#define CPC() asm volatile("cp.async.commit_group;" ::: "memory")
#define CPWAIT(N) asm volatile("cp.async.wait_group %0;" :: "n"(N) : "memory")

#define MMA_TF32(c, a0, a1, a2, a3, b0, b1) \
    asm volatile("mma.sync.aligned.m16n8k8.row.col.f32.tf32.tf32.f32 " \
        "{%0,%1,%2,%3},{%4,%5,%6,%7},{%8,%9},{%0,%1,%2,%3};" \
        : "+f"((c)[0]), "+f"((c)[1]), "+f"((c)[2]), "+f"((c)[3]) \
        : "r"(a0), "r"(a1), "r"(a2), "r"(a3), "r"(b0), "r"(b1))

#define CVT_RNA(u, f) asm("cvt.rna.tf32.f32 %0, %1;" : "=r"(u) : "f"(f))
#define PACK_F16X2(u, lo, hi) \
    asm("cvt.rn.f16x2.f32 %0, %1, %2;" : "=r"(u) : "f"(hi), "f"(lo))

__device__ __forceinline__ uint32_t smem_u32(const void* p){
    uint32_t a;
    asm("{ .reg .u64 t; cvta.to.shared.u64 t, %1; cvt.u32.u64 %0, t; }" : "=r"(a) : "l"(p));
    return a;
}

// ---- kernel 0a: round Q/K to tf32-RNA, transpose to [h][tok][d] ----
__global__ void __launch_bounds__(256, 4)
preround_kernel(const float* __restrict__ Qg, const float* __restrict__ Kg)
{
    const int z = blockIdx.z, h = blockIdx.y;
    const int r = blockIdx.x * 8 + (threadIdx.x >> 5);
    const int c = threadIdx.x & 31;
    const float4* src = (const float4*)(z == 0 ? Qg : Kg);
    uint4* dst = (uint4*)(z == 0 ? Qp : Kp);
    float4 v = src[((size_t)r * HQ + h) * 32 + c];
    uint4 u;
    CVT_RNA(u.x, v.x); CVT_RNA(u.y, v.y); CVT_RNA(u.z, v.z); CVT_RNA(u.w, v.w);
    dst[((size_t)h * QLEN + r) * 32 + c] = u;
}

// ---- kernel 0b: V -> Vtg[h][d][kv] with RNA rounding ----
__global__ void __launch_bounds__(256, 4)
vtrans_kernel(const float* __restrict__ Vg)
{
    __shared__ float t[32][33];
    const int h = blockIdx.z;
    const int r0 = blockIdx.x * 32, d0 = blockIdx.y * 32;
    const int x = threadIdx.x & 31, y = threadIdx.x >> 5;
#pragma unroll
    for (int k = 0; k < 4; k++){
        int r = r0 + y + k * 8;
        float v = Vg[((size_t)r * HQ + h) * 128 + d0 + x];
        uint32_t u; CVT_RNA(u, v);
        t[y + k * 8][x] = __uint_as_float(u);
    }
    __syncthreads();
#pragma unroll
    for (int k = 0; k < 4; k++){
        int d = d0 + y + k * 8;
        Vtg[((size_t)h * 128 + d) * KVLEN + r0 + x] = t[x][y + k * 8];
    }
}

__global__ void zero_kernel(float* __restrict__ p, int n)
{
    int i = blockIdx.x * blockDim.x + threadIdx.x;
    if (i < n) p[i] = 0.0f;
}

// =================== QK kernel: BN=128, paired-k LDS.128 ===================
#define QK_NT   512
#define PQK     144        // floats; 144 % 32 == 16 -> conflict-free LDS.128 phases
#define QK_RED  0
#define QK_Q    2048
#define QK_SLOT (128 * PQK * 4)            // 73728
#define QK_K0   (2048 + QK_SLOT)           // 75776
#define QK_TOTAL (QK_K0 + 2 * QK_SLOT)     // 223232

__device__ __forceinline__ void qk_load_tile(char* base, const float4* g,
                                             size_t rowBase, int tid){
    for (int i = tid; i < 128 * 32; i += QK_NT){
        int r = i >> 5, c = i & 31;
        CPA16(smem_u32(base + r * (PQK * 4) + c * 16), &g[(rowBase + r) * 32 + c]);
    }
}

__global__ void __launch_bounds__(QK_NT, 1)
qk_kernel()
{
    extern __shared__ char sm[];
    const int tid = threadIdx.x, w = tid >> 5, lid = tid & 31;
    const int tq = lid >> 2, tr = lid & 3;
    const int h = blockIdx.y;
    const int qi = (gridDim.x - 1) - blockIdx.x;       // heavy tiles first
    const int q0 = qi * 128;
    const int nt = qi + 1;                              // 128-kv tiles
    const float scale = 0.08838834764831845f;

    const int wq = w & 3;      // 32-row block
    const int wn = w >> 2;     // 32-col kv block

    float* sQ = (float*)(sm + QK_Q);
    const float4* gq = (const float4*)Qp;
    const float4* gk = (const float4*)Kp;

    qk_load_tile(sm + QK_Q, gq, (size_t)h * QLEN + q0, tid);
    qk_load_tile(sm + QK_K0, gk, (size_t)h * KVLEN, tid);
    CPC();

    float rsum[4] = {0.f, 0.f, 0.f, 0.f};

    for (int t = 0; t < nt; ++t){
        const int cur = t & 1;
        const int k0 = t * 128;

        CPWAIT(0);
        __syncthreads();
        if (t + 1 < nt){
            qk_load_tile(sm + QK_K0 + (cur ^ 1) * QK_SLOT, gk,
                         (size_t)h * KVLEN + (t + 1) * 128, tid);
            CPC();
        }

        float accs[2][4][4];
#pragma unroll
        for (int mf = 0; mf < 2; ++mf)
#pragma unroll
            for (int nf = 0; nf < 4; ++nf)
#pragma unroll
                for (int x = 0; x < 4; ++x) accs[mf][nf][x] = 0.f;

        const float* Kb = (const float*)(sm + QK_K0 + cur * QK_SLOT);
        // paired k-steps: uint4 at cols 16jj+4tr serves 2 MMAs
#pragma unroll
        for (int jj = 0; jj < 8; ++jj){
            const int col = jj * 16 + 4 * tr;
            uint4 alo[2], ahi[2], b[4];
#pragma unroll
            for (int mf = 0; mf < 2; ++mf){
                alo[mf] = *(const uint4*)(sQ + (wq*32 + mf*16 + tq) * PQK + col);
                ahi[mf] = *(const uint4*)(sQ + (wq*32 + mf*16 + 8 + tq) * PQK + col);
            }
#pragma unroll
            for (int nf = 0; nf < 4; ++nf)
                b[nf] = *(const uint4*)(Kb + (wn*32 + nf*8 + tq) * PQK + col);
#pragma unroll
            for (int mf = 0; mf < 2; ++mf)
#pragma unroll
                for (int nf = 0; nf < 4; ++nf){
                    MMA_TF32(accs[mf][nf], alo[mf].x, ahi[mf].x, alo[mf].y, ahi[mf].y,
                             b[nf].x, b[nf].y);
                    MMA_TF32(accs[mf][nf], alo[mf].z, ahi[mf].z, alo[mf].w, ahi[mf].w,
                             b[nf].z, b[nf].w);
                }
        }

        // epilogue: exp, rsum, E fp16 store
#pragma unroll
        for (int mf = 0; mf < 2; ++mf)
#pragma unroll
            for (int nf = 0; nf < 4; ++nf){
                const int kvb = k0 + wn*32 + nf*8 + 2*tr;
#pragma unroll
                for (int hf = 0; hf < 2; ++hf){
                    const int qrow = q0 + wq*32 + mf*16 + hf*8 + tq;
                    float e0 = (kvb     <= qrow) ? __expf(accs[mf][nf][hf*2    ] * scale) : 0.f;
                    float e1 = (kvb + 1 <= qrow) ? __expf(accs[mf][nf][hf*2 + 1] * scale) : 0.f;
                    rsum[mf*2 + hf] += e0 + e1;
                    uint32_t pk;
                    PACK_F16X2(pk, e0, e1);
                    *(uint32_t*)&Ep[((size_t)h * QLEN + qrow) * KVLEN + kvb] = pk;
                }
            }
    }

    // reduce row sums: tr lanes, then 4 wn groups via smem
#pragma unroll
    for (int r = 0; r < 4; ++r){
        rsum[r] += __shfl_xor_sync(0xffffffffu, rsum[r], 1);
        rsum[r] += __shfl_xor_sync(0xffffffffu, rsum[r], 2);
    }
    float* red = (float*)(sm + QK_RED);
    if (tr == 0){
#pragma unroll
        for (int r = 0; r < 4; ++r){
            const int row = wq*32 + (r >> 1)*16 + (r & 1)*8 + tq;
            red[wn * 128 + row] = rsum[r];
        }
    }
    __syncthreads();
    if (tid < 128){
        float s = (red[tid] + red[128 + tid]) + (red[256 + tid] + red[384 + tid]);
        invl_g[h * QLEN + q0 + tid] = 1.0f / s;
    }
}

// =================== PV GEMM: O = (E fp16 -> tf32) * Vt ===================
#define PV_NT   256
#define PE2     72
#define PVT     72
#define PV_E0   0
#define PV_EB   18432
#define PV_V0   36864
#define PV_VB   36864
#define PV_TOTAL 110592

__device__ __forceinline__ void pv_load(char* sm, int buf, int k0, int h, int q0, int tid){
    char* eb = sm + PV_E0 + buf * PV_EB;
    for (int i = tid; i < 128 * 8; i += PV_NT){
        int r = i >> 3, c = i & 7;
        CPA16(smem_u32(eb + r * (PE2 * 2) + c * 16),
              &Ep[((size_t)h * QLEN + q0 + r) * KVLEN + k0 + c * 8]);
    }
    char* vb = sm + PV_V0 + buf * PV_VB;
    for (int i = tid; i < 128 * 16; i += PV_NT){
        int d = i >> 4, c = i & 15;
        CPA16(smem_u32(vb + d * (PVT * 4) + c * 16),
              &Vtg[((size_t)h * 128 + d) * KVLEN + k0 + c * 4]);
    }
}

__global__ void __launch_bounds__(PV_NT, 2)
pv_kernel(float* __restrict__ Outg)
{
    extern __shared__ char sm[];
    const int tid = threadIdx.x, w = tid >> 5, lid = tid & 31;
    const int tq = lid >> 2, tr = lid & 3;
    const int h = blockIdx.y;
    const int qi = (gridDim.x - 1) - blockIdx.x;
    const int q0 = qi * 128;
    const int nt = 2 * qi + 2;

    const int wq = w & 3;      // 32-row block
    const int wd = w >> 2;     // 64-d block

    pv_load(sm, 0, 0, h, q0, tid);
    CPC();

    float acco[2][8][4];
#pragma unroll
    for (int mf = 0; mf < 2; ++mf)
#pragma unroll
        for (int nf = 0; nf < 8; ++nf)
#pragma unroll
            for (int x = 0; x < 4; ++x) acco[mf][nf][x] = 0.f;

    for (int t = 0; t < nt; ++t){
        const int cur = t & 1;
        CPWAIT(0);
        __syncthreads();
        if (t + 1 < nt){ pv_load(sm, cur ^ 1, (t + 1) * 64, h, q0, tid); CPC(); }

        const __half* sE = (const __half*)(sm + PV_E0 + cur * PV_EB);
        const float*  sV = (const float*)(sm + PV_V0 + cur * PV_VB);
#pragma unroll
        for (int j = 0; j < 8; ++j){
            const int kc = j * 8 + 2 * tr;
            uint32_t a0[2], a1[2], a2[2], a3[2];
#pragma unroll
            for (int mf = 0; mf < 2; ++mf){
                __half2 lo = *(const __half2*)(sE + (wq*32 + mf*16 + tq) * PE2 + kc);
                __half2 hi = *(const __half2*)(sE + (wq*32 + mf*16 + 8 + tq) * PE2 + kc);
                float2 flo = __half22float2(lo);
                float2 fhi = __half22float2(hi);
                a0[mf] = __float_as_uint(flo.x);
                a1[mf] = __float_as_uint(fhi.x);
                a2[mf] = __float_as_uint(flo.y);
                a3[mf] = __float_as_uint(fhi.y);
            }
            uint2 b[8];
#pragma unroll
            for (int nf = 0; nf < 8; ++nf)
                b[nf] = *(const uint2*)(sV + (wd*64 + nf*8 + tq) * PVT + kc);
#pragma unroll
            for (int mf = 0; mf < 2; ++mf)
#pragma unroll
                for (int nf = 0; nf < 8; ++nf)
                    MMA_TF32(acco[mf][nf], a0[mf], a1[mf], a2[mf], a3[mf],
                             b[nf].x, b[nf].y);
        }
    }

#pragma unroll
    for (int mf = 0; mf < 2; ++mf)
#pragma unroll
        for (int hf = 0; hf < 2; ++hf){
            const int row = wq*32 + mf*16 + hf*8 + tq;
            const float iv = invl_g[h * QLEN + q0 + row];
#pragma unroll
            for (int nf = 0; nf < 8; ++nf){
                const int d = wd*64 + nf*8 + 2*tr;
                *(float2*)&Outg[((size_t)(q0 + row) * HQ + h) * 128 + d] =
                    make_float2(acco[mf][nf][hf*2] * iv, acco[mf][nf][hf*2 + 1] * iv);
            }
        }
}

// ---- colsum: roco over fp16 E[h][q][kv], q-chunked, MLP=4 ----
__global__ void __launch_bounds__(256, 8)
roco_colsum_kernel(float* __restrict__ roco, float* __restrict__ roco_sq)
{
    __shared__ float ivs[256];
    const int h = blockIdx.y, z = blockIdx.z;
    const int qlo = z * 256, qhi = qlo + 256;
    const int kv = blockIdx.x * 512 + threadIdx.x * 2;

    if (threadIdx.x < 64)
        ((float4*)ivs)[threadIdx.x] =
            ((const float4*)&invl_g[h * QLEN + qlo])[threadIdx.x];
    __syncthreads();

    const int qstart = (kv >> 7) << 7;
    if (qstart >= qhi) return;
    int q = qstart > qlo ? qstart : qlo;

    float cs0 = 0.f, cq0 = 0.f, cs1 = 0.f, cq1 = 0.f;
    const uint32_t* Eb = (const uint32_t*)&Ep[((size_t)h * QLEN) * KVLEN + kv];
    const size_t K2 = KVLEN / 2;
    for (; q + 3 < qhi; q += 4){
        uint32_t u0 = Eb[(size_t)q * K2];
        uint32_t u1 = Eb[(size_t)(q + 1) * K2];
        uint32_t u2 = Eb[(size_t)(q + 2) * K2];
        uint32_t u3 = Eb[(size_t)(q + 3) * K2];
        float4 iv = *(const float4*)&ivs[q - qlo];
        float2 f0 = __half22float2(*(const __half2*)&u0);
        float2 f1 = __half22float2(*(const __half2*)&u1);
        float2 f2 = __half22float2(*(const __half2*)&u2);
        float2 f3 = __half22float2(*(const __half2*)&u3);
        float a0 = f0.x * iv.x, b0 = f0.y * iv.x;
        float a1 = f1.x * iv.y, b1 = f1.y * iv.y;
        float a2 = f2.x * iv.z, b2 = f2.y * iv.z;
        float a3 = f3.x * iv.w, b3 = f3.y * iv.w;
        cs0 += (a0 + a1) + (a2 + a3);
        cs1 += (b0 + b1) + (b2 + b3);
        cq0 = fmaf(a0, a0, cq0); cq0 = fmaf(a1, a1, cq0);
        cq0 = fmaf(a2, a2, cq0); cq0 = fmaf(a3, a3, cq0);
        cq1 = fmaf(b0, b0, cq1); cq1 = fmaf(b1, b1, cq1);
        cq1 = fmaf(b2, b2, cq1); cq1 = fmaf(b3, b3, cq1);
    }
    atomicAdd(&roco[h * QLEN + kv],        cs0);
    atomicAdd(&roco[h * QLEN + kv + 1],    cs1);
    atomicAdd(&roco_sq[h * QLEN + kv],     cq0);
    atomicAdd(&roco_sq[h * QLEN + kv + 1], cq1);
}

extern "C" void kernel_launch(void* const* d_in, const int* in_sizes, int n_in,
                              void* d_out, int out_size)
{
    const float* Qg = (const float*)d_in[0];
    const float* Kg = (const float*)d_in[1];
    const float* Vg = (const float*)d_in[2];
    float* Outg    = (float*)d_out;
    float* roco    = Outg + (size_t)QLEN * HQ * 128;    // 8388608
    float* roco_sq = roco + HQ * QLEN;                  // +65536

    cudaFuncSetAttribute(qk_kernel,
                         cudaFuncAttributeMaxDynamicSharedMemorySize, QK_TOTAL);
    cudaFuncSetAttribute(pv_kernel,
                         cudaFuncAttributeMaxDynamicSharedMemorySize, PV_TOTAL);

    dim3 gpr(QLEN / 8, HQ, 2);
    preround_kernel<<<gpr, 256>>>(Qg, Kg);

    dim3 gvt(KVLEN / 32, 128 / 32, HQ);
    vtrans_kernel<<<gvt, 256>>>(Vg);

    const int nz = 2 * HQ * QLEN;
    zero_kernel<<<(nz + 255) / 256, 256>>>(roco, nz);

    dim3 g1(QLEN / 128, HQ);        // (16, 32)
    qk_kernel<<<g1, QK_NT, QK_TOTAL>>>();

    pv_kernel<<<g1, PV_NT, PV_TOTAL>>>(Outg);

    dim3 g2(KVLEN / 512, HQ, 8);    // (4, 32, 8)
    roco_colsum_kernel<<<g2, 256>>>(roco, roco_sq);
}

// round 16
// speedup vs baseline: 5.2564x; 1.2595x over previous
#include <cuda_runtime.h>
#include <cuda_fp16.h>
#include <cstdint>

#define HQ    32
#define QLEN  2048
#define KVLEN 2048

// rounded, head-major copies
__device__ float Qp[(size_t)HQ * QLEN * 128];
__device__ float Kp[(size_t)HQ * KVLEN * 128];
__device__ __half Vhg[(size_t)HQ * 128 * KVLEN];    // [h][d][kv], fp16
// [h][q][kv] unnormalized exp-scores, fp16
__device__ __half Ep[(size_t)HQ * QLEN * KVLEN];
__device__ float invl_g[HQ * QLEN];

#define CPA16(dst, src) \
    asm volatile("cp.async.cg.shared.global [%0], [%1], 16;" :: "r"(dst), "l"(src))
#define CPC() asm volatile("cp.async.commit_group;" ::: "memory")
#define CPWAIT(N) asm volatile("cp.async.wait_group %0;" :: "n"(N) : "memory")

#define MMA_TF32(c, a0, a1, a2, a3, b0, b1) \
    asm volatile("mma.sync.aligned.m16n8k8.row.col.f32.tf32.tf32.f32 " \
        "{%0,%1,%2,%3},{%4,%5,%6,%7},{%8,%9},{%0,%1,%2,%3};" \
        : "+f"((c)[0]), "+f"((c)[1]), "+f"((c)[2]), "+f"((c)[3]) \
        : "r"(a0), "r"(a1), "r"(a2), "r"(a3), "r"(b0), "r"(b1))

#define MMA_F16(c, a0, a1, a2, a3, b0, b1) \
    asm volatile("mma.sync.aligned.m16n8k16.row.col.f32.f16.f16.f32 " \
        "{%0,%1,%2,%3},{%4,%5,%6,%7},{%8,%9},{%0,%1,%2,%3};" \
        : "+f"((c)[0]), "+f"((c)[1]), "+f"((c)[2]), "+f"((c)[3]) \
        : "r"(a0), "r"(a1), "r"(a2), "r"(a3), "r"(b0), "r"(b1))

#define CVT_RNA(u, f) asm("cvt.rna.tf32.f32 %0, %1;" : "=r"(u) : "f"(f))
#define PACK_F16X2(u, lo, hi) \
    asm("cvt.rn.f16x2.f32 %0, %1, %2;" : "=r"(u) : "f"(hi), "f"(lo))

__device__ __forceinline__ uint32_t smem_u32(const void* p){
    uint32_t a;
    asm("{ .reg .u64 t; cvta.to.shared.u64 t, %1; cvt.u32.u64 %0, t; }" : "=r"(a) : "l"(p));
    return a;
}

// ---- kernel 0a: round Q/K to tf32-RNA, transpose to [h][tok][d] ----
__global__ void __launch_bounds__(256, 4)
preround_kernel(const float* __restrict__ Qg, const float* __restrict__ Kg)
{
    const int z = blockIdx.z, h = blockIdx.y;
    const int r = blockIdx.x * 8 + (threadIdx.x >> 5);
    const int c = threadIdx.x & 31;
    const float4* src = (const float4*)(z == 0 ? Qg : Kg);
    uint4* dst = (uint4*)(z == 0 ? Qp : Kp);
    float4 v = src[((size_t)r * HQ + h) * 32 + c];
    uint4 u;
    CVT_RNA(u.x, v.x); CVT_RNA(u.y, v.y); CVT_RNA(u.z, v.z); CVT_RNA(u.w, v.w);
    dst[((size_t)h * QLEN + r) * 32 + c] = u;
}

// ---- kernel 0b: V -> Vhg[h][d][kv] fp16 (smem tile transpose) ----
__global__ void __launch_bounds__(256, 4)
vtrans_kernel(const float* __restrict__ Vg)
{
    __shared__ float t[32][33];
    const int h = blockIdx.z;
    const int r0 = blockIdx.x * 32, d0 = blockIdx.y * 32;
    const int x = threadIdx.x & 31, y = threadIdx.x >> 5;
#pragma unroll
    for (int k = 0; k < 4; k++){
        int r = r0 + y + k * 8;
        t[y + k * 8][x] = Vg[((size_t)r * HQ + h) * 128 + d0 + x];
    }
    __syncthreads();
    const int xk = threadIdx.x & 15;          // kv pair
    const int yy = threadIdx.x >> 4;          // 16 d values
#pragma unroll
    for (int k = 0; k < 2; k++){
        int d = d0 + yy + k * 16;
        __half2 hv = __floats2half2_rn(t[2 * xk][yy + k * 16], t[2 * xk + 1][yy + k * 16]);
        *(__half2*)&Vhg[((size_t)h * 128 + d) * KVLEN + r0 + 2 * xk] = hv;
    }
}

__global__ void zero_kernel(float* __restrict__ p, int n)
{
    int i = blockIdx.x * blockDim.x + threadIdx.x;
    if (i < n) p[i] = 0.0f;
}

// =================== QK kernel: BN=128, paired-k LDS.128 ===================
#define QK_NT   512
#define PQK     144
#define QK_RED  0
#define QK_Q    2048
#define QK_SLOT (128 * PQK * 4)
#define QK_K0   (2048 + QK_SLOT)
#define QK_TOTAL (QK_K0 + 2 * QK_SLOT)

__device__ __forceinline__ void qk_load_tile(char* base, const float4* g,
                                             size_t rowBase, int tid){
    for (int i = tid; i < 128 * 32; i += QK_NT){
        int r = i >> 5, c = i & 31;
        CPA16(smem_u32(base + r * (PQK * 4) + c * 16), &g[(rowBase + r) * 32 + c]);
    }
}

__global__ void __launch_bounds__(QK_NT, 1)
qk_kernel()
{
    extern __shared__ char sm[];
    const int tid = threadIdx.x, w = tid >> 5, lid = tid & 31;
    const int tq = lid >> 2, tr = lid & 3;
    const int h = blockIdx.y;
    const int qi = (gridDim.x - 1) - blockIdx.x;
    const int q0 = qi * 128;
    const int nt = qi + 1;
    const float scale = 0.08838834764831845f;

    const int wq = w & 3;
    const int wn = w >> 2;

    float* sQ = (float*)(sm + QK_Q);
    const float4* gq = (const float4*)Qp;
    const float4* gk = (const float4*)Kp;

    qk_load_tile(sm + QK_Q, gq, (size_t)h * QLEN + q0, tid);
    qk_load_tile(sm + QK_K0, gk, (size_t)h * KVLEN, tid);
    CPC();

    float rsum[4] = {0.f, 0.f, 0.f, 0.f};

    for (int t = 0; t < nt; ++t){
        const int cur = t & 1;
        const int k0 = t * 128;

        CPWAIT(0);
        __syncthreads();
        if (t + 1 < nt){
            qk_load_tile(sm + QK_K0 + (cur ^ 1) * QK_SLOT, gk,
                         (size_t)h * KVLEN + (t + 1) * 128, tid);
            CPC();
        }

        float accs[2][4][4];
#pragma unroll
        for (int mf = 0; mf < 2; ++mf)
#pragma unroll
            for (int nf = 0; nf < 4; ++nf)
#pragma unroll
                for (int x = 0; x < 4; ++x) accs[mf][nf][x] = 0.f;

        const float* Kb = (const float*)(sm + QK_K0 + cur * QK_SLOT);
#pragma unroll
        for (int jj = 0; jj < 8; ++jj){
            const int col = jj * 16 + 4 * tr;
            uint4 alo[2], ahi[2], b[4];
#pragma unroll
            for (int mf = 0; mf < 2; ++mf){
                alo[mf] = *(const uint4*)(sQ + (wq*32 + mf*16 + tq) * PQK + col);
                ahi[mf] = *(const uint4*)(sQ + (wq*32 + mf*16 + 8 + tq) * PQK + col);
            }
#pragma unroll
            for (int nf = 0; nf < 4; ++nf)
                b[nf] = *(const uint4*)(Kb + (wn*32 + nf*8 + tq) * PQK + col);
#pragma unroll
            for (int mf = 0; mf < 2; ++mf)
#pragma unroll
                for (int nf = 0; nf < 4; ++nf){
                    MMA_TF32(accs[mf][nf], alo[mf].x, ahi[mf].x, alo[mf].y, ahi[mf].y,
                             b[nf].x, b[nf].y);
                    MMA_TF32(accs[mf][nf], alo[mf].z, ahi[mf].z, alo[mf].w, ahi[mf].w,
                             b[nf].z, b[nf].w);
                }
        }

        // epilogue: exp, rsum, E fp16 store (mask only on diagonal tile)
        if (t < nt - 1){
#pragma unroll
            for (int mf = 0; mf < 2; ++mf)
#pragma unroll
                for (int nf = 0; nf < 4; ++nf){
                    const int kvb = k0 + wn*32 + nf*8 + 2*tr;
#pragma unroll
                    for (int hf = 0; hf < 2; ++hf){
                        const int qrow = q0 + wq*32 + mf*16 + hf*8 + tq;
                        float e0 = __expf(accs[mf][nf][hf*2    ] * scale);
                        float e1 = __expf(accs[mf][nf][hf*2 + 1] * scale);
                        rsum[mf*2 + hf] += e0 + e1;
                        uint32_t pk;
                        PACK_F16X2(pk, e0, e1);
                        *(uint32_t*)&Ep[((size_t)h * QLEN + qrow) * KVLEN + kvb] = pk;
                    }
                }
        } else {
#pragma unroll
            for (int mf = 0; mf < 2; ++mf)
#pragma unroll
                for (int nf = 0; nf < 4; ++nf){
                    const int kvb = k0 + wn*32 + nf*8 + 2*tr;
#pragma unroll
                    for (int hf = 0; hf < 2; ++hf){
                        const int qrow = q0 + wq*32 + mf*16 + hf*8 + tq;
                        float e0 = (kvb     <= qrow) ? __expf(accs[mf][nf][hf*2    ] * scale) : 0.f;
                        float e1 = (kvb + 1 <= qrow) ? __expf(accs[mf][nf][hf*2 + 1] * scale) : 0.f;
                        rsum[mf*2 + hf] += e0 + e1;
                        uint32_t pk;
                        PACK_F16X2(pk, e0, e1);
                        *(uint32_t*)&Ep[((size_t)h * QLEN + qrow) * KVLEN + kvb] = pk;
                    }
                }
        }
    }

#pragma unroll
    for (int r = 0; r < 4; ++r){
        rsum[r] += __shfl_xor_sync(0xffffffffu, rsum[r], 1);
        rsum[r] += __shfl_xor_sync(0xffffffffu, rsum[r], 2);
    }
    float* red = (float*)(sm + QK_RED);
    if (tr == 0){
#pragma unroll
        for (int r = 0; r < 4; ++r){
            const int row = wq*32 + (r >> 1)*16 + (r & 1)*8 + tq;
            red[wn * 128 + row] = rsum[r];
        }
    }
    __syncthreads();
    if (tid < 128){
        float s = (red[tid] + red[128 + tid]) + (red[256 + tid] + red[384 + tid]);
        invl_g[h * QLEN + q0 + tid] = 1.0f / s;
    }
}

// =================== PV GEMM (fp16): O = E * V^T ===================
#define PV_NT   256
#define PEH     80                     // halves pitch, conflict-free
#define PV_EB   (128 * PEH * 2)        // 20480
#define PV_V0   (2 * PV_EB)            // 40960
#define PV_VB   (128 * PEH * 2)
#define PV_TOTAL (PV_V0 + 2 * PV_VB)   // 81920

__device__ __forceinline__ void pv_load(char* sm, int buf, int k0, int h, int q0, int tid){
    char* eb = sm + buf * PV_EB;
    for (int i = tid; i < 128 * 8; i += PV_NT){
        int r = i >> 3, c = i & 7;
        CPA16(smem_u32(eb + r * (PEH * 2) + c * 16),
              &Ep[((size_t)h * QLEN + q0 + r) * KVLEN + k0 + c * 8]);
    }
    char* vb = sm + PV_V0 + buf * PV_VB;
    for (int i = tid; i < 128 * 8; i += PV_NT){
        int d = i >> 3, c = i & 7;
        CPA16(smem_u32(vb + d * (PEH * 2) + c * 16),
              &Vhg[((size_t)h * 128 + d) * KVLEN + k0 + c * 8]);
    }
}

__global__ void __launch_bounds__(PV_NT, 2)
pv_kernel(float* __restrict__ Outg)
{
    extern __shared__ char sm[];
    const int tid = threadIdx.x, w = tid >> 5, lid = tid & 31;
    const int tq = lid >> 2, tr = lid & 3;
    const int h = blockIdx.y;
    const int qi = (gridDim.x - 1) - blockIdx.x;
    const int q0 = qi * 128;
    const int nt = 2 * qi + 2;

    const int wq = w & 3;      // 32-row block
    const int wd = w >> 2;     // 64-d block

    pv_load(sm, 0, 0, h, q0, tid);
    CPC();

    float acco[2][8][4];
#pragma unroll
    for (int mf = 0; mf < 2; ++mf)
#pragma unroll
        for (int nf = 0; nf < 8; ++nf)
#pragma unroll
            for (int x = 0; x < 4; ++x) acco[mf][nf][x] = 0.f;

    for (int t = 0; t < nt; ++t){
        const int cur = t & 1;
        CPWAIT(0);
        __syncthreads();
        if (t + 1 < nt){ pv_load(sm, cur ^ 1, (t + 1) * 64, h, q0, tid); CPC(); }

        const __half* sE = (const __half*)(sm + cur * PV_EB);
        const __half* sV = (const __half*)(sm + PV_V0 + cur * PV_VB);
        // k-perm per 16-chunk: lanes {2tr,2tr+1}->kv {4tr,4tr+1}; {8+2tr,+1}->{4tr+2,+3}
#pragma unroll
        for (int cc = 0; cc < 4; ++cc){
            const int kb = cc * 16 + 4 * tr;
            uint2 a[2][2];
#pragma unroll
            for (int mf = 0; mf < 2; ++mf){
                a[mf][0] = *(const uint2*)(sE + (wq*32 + mf*16 + tq) * PEH + kb);
                a[mf][1] = *(const uint2*)(sE + (wq*32 + mf*16 + 8 + tq) * PEH + kb);
            }
#pragma unroll
            for (int half = 0; half < 2; ++half){
                uint2 b[4];
#pragma unroll
                for (int f = 0; f < 4; ++f)
                    b[f] = *(const uint2*)(sV + (wd*64 + (half*4 + f)*8 + tq) * PEH + kb);
#pragma unroll
                for (int mf = 0; mf < 2; ++mf)
#pragma unroll
                    for (int f = 0; f < 4; ++f)
                        MMA_F16(acco[mf][half*4 + f],
                                a[mf][0].x, a[mf][1].x, a[mf][0].y, a[mf][1].y,
                                b[f].x, b[f].y);
            }
        }
    }

#pragma unroll
    for (int mf = 0; mf < 2; ++mf)
#pragma unroll
        for (int hf = 0; hf < 2; ++hf){
            const int row = wq*32 + mf*16 + hf*8 + tq;
            const float iv = invl_g[h * QLEN + q0 + row];
#pragma unroll
            for (int nf = 0; nf < 8; ++nf){
                const int d = wd*64 + nf*8 + 2*tr;
                *(float2*)&Outg[((size_t)(q0 + row) * HQ + h) * 128 + d] =
                    make_float2(acco[mf][nf][hf*2] * iv, acco[mf][nf][hf*2 + 1] * iv);
            }
        }
}

// ---- colsum: roco over fp16 E[h][q][kv], q-chunked, MLP=8 ----
__global__ void __launch_bounds__(256, 8)
roco_colsum_kernel(float* __restrict__ roco, float* __restrict__ roco_sq)
{
    __shared__ float ivs[256];
    const int h = blockIdx.y, z = blockIdx.z;
    const int qlo = z * 256, qhi = qlo + 256;
    const int kv = blockIdx.x * 512 + threadIdx.x * 2;

    if (threadIdx.x < 64)
        ((float4*)ivs)[threadIdx.x] =
            ((const float4*)&invl_g[h * QLEN + qlo])[threadIdx.x];
    __syncthreads();

    const int qstart = (kv >> 7) << 7;
    if (qstart >= qhi) return;
    int q = qstart > qlo ? qstart : qlo;

    float cs0 = 0.f, cq0 = 0.f, cs1 = 0.f, cq1 = 0.f;
    const uint32_t* Eb = (const uint32_t*)&Ep[((size_t)h * QLEN) * KVLEN + kv];
    const size_t K2 = KVLEN / 2;
    for (; q + 7 < qhi; q += 8){
        uint32_t u[8];
#pragma unroll
        for (int i = 0; i < 8; ++i) u[i] = Eb[(size_t)(q + i) * K2];
        float4 iva = *(const float4*)&ivs[q - qlo];
        float4 ivb4 = *(const float4*)&ivs[q - qlo + 4];
        float ivv[8] = {iva.x, iva.y, iva.z, iva.w, ivb4.x, ivb4.y, ivb4.z, ivb4.w};
#pragma unroll
        for (int i = 0; i < 8; ++i){
            float2 f = __half22float2(*(const __half2*)&u[i]);
            float a = f.x * ivv[i], b = f.y * ivv[i];
            cs0 += a; cs1 += b;
            cq0 = fmaf(a, a, cq0); cq1 = fmaf(b, b, cq1);
        }
    }
    atomicAdd(&roco[h * QLEN + kv],        cs0);
    atomicAdd(&roco[h * QLEN + kv + 1],    cs1);
    atomicAdd(&roco_sq[h * QLEN + kv],     cq0);
    atomicAdd(&roco_sq[h * QLEN + kv + 1], cq1);
}

extern "C" void kernel_launch(void* const* d_in, const int* in_sizes, int n_in,
                              void* d_out, int out_size)
{
    const float* Qg = (const float*)d_in[0];
    const float* Kg = (const float*)d_in[1];
    const float* Vg = (const float*)d_in[2];
    float* Outg    = (float*)d_out;
    float* roco    = Outg + (size_t)QLEN * HQ * 128;    // 8388608
    float* roco_sq = roco + HQ * QLEN;                  // +65536

    cudaFuncSetAttribute(qk_kernel,
                         cudaFuncAttributeMaxDynamicSharedMemorySize, QK_TOTAL);
    cudaFuncSetAttribute(pv_kernel,
                         cudaFuncAttributeMaxDynamicSharedMemorySize, PV_TOTAL);

    dim3 gpr(QLEN / 8, HQ, 2);
    preround_kernel<<<gpr, 256>>>(Qg, Kg);

    dim3 gvt(KVLEN / 32, 128 / 32, HQ);
    vtrans_kernel<<<gvt, 256>>>(Vg);

    const int nz = 2 * HQ * QLEN;
    zero_kernel<<<(nz + 255) / 256, 256>>>(roco, nz);

    dim3 g1(QLEN / 128, HQ);        // (16, 32)
    qk_kernel<<<g1, QK_NT, QK_TOTAL>>>();

    pv_kernel<<<g1, PV_NT, PV_TOTAL>>>(Outg);

    dim3 g2(KVLEN / 512, HQ, 8);    // (4, 32, 8)
    roco_colsum_kernel<<<g2, 256>>>(roco, roco_sq);
}

// round 17
// speedup vs baseline: 5.5323x; 1.0525x over previous
#include <cuda_runtime.h>
#include <cuda_fp16.h>
#include <cstdint>

#define HQ    32
#define QLEN  2048
#define KVLEN 2048

// rounded, head-major copies
__device__ float Qp[(size_t)HQ * QLEN * 128];
__device__ float Kp[(size_t)HQ * KVLEN * 128];
__device__ __half Vhg[(size_t)HQ * 128 * KVLEN];    // [h][d][kv-interleaved], fp16
// fragment-native E: tile = (h, qi, t) -> 2048 uint4; u4 idx = warp*128 + fg*32 + lid
__device__ uint4 Ef[(size_t)HQ * 136 * 2048];
__device__ float invl_g[HQ * QLEN];

#define CPA16(dst, src) \
    asm volatile("cp.async.cg.shared.global [%0], [%1], 16;" :: "r"(dst), "l"(src))
#define CPC() asm volatile("cp.async.commit_group;" ::: "memory")
#define CPWAIT(N) asm volatile("cp.async.wait_group %0;" :: "n"(N) : "memory")

#define MMA_TF32(c, a0, a1, a2, a3, b0, b1) \
    asm volatile("mma.sync.aligned.m16n8k8.row.col.f32.tf32.tf32.f32 " \
        "{%0,%1,%2,%3},{%4,%5,%6,%7},{%8,%9},{%0,%1,%2,%3};" \
        : "+f"((c)[0]), "+f"((c)[1]), "+f"((c)[2]), "+f"((c)[3]) \
        : "r"(a0), "r"(a1), "r"(a2), "r"(a3), "r"(b0), "r"(b1))

#define MMA_F16(c, a0, a1, a2, a3, b0, b1) \
    asm volatile("mma.sync.aligned.m16n8k16.row.col.f32.f16.f16.f32 " \
        "{%0,%1,%2,%3},{%4,%5,%6,%7},{%8,%9},{%0,%1,%2,%3};" \
        : "+f"((c)[0]), "+f"((c)[1]), "+f"((c)[2]), "+f"((c)[3]) \
        : "r"(a0), "r"(a1), "r"(a2), "r"(a3), "r"(b0), "r"(b1))

#define CVT_RNA(u, f) asm("cvt.rna.tf32.f32 %0, %1;" : "=r"(u) : "f"(f))
#define PACK_F16X2(u, lo, hi) \
    asm("cvt.rn.f16x2.f32 %0, %1, %2;" : "=r"(u) : "f"(hi), "f"(lo))

__device__ __forceinline__ uint32_t smem_u32(const void* p){
    uint32_t a;
    asm("{ .reg .u64 t; cvta.to.shared.u64 t, %1; cvt.u32.u64 %0, t; }" : "=r"(a) : "l"(p));
    return a;
}

// ---- kernel 0a: round Q/K to tf32-RNA, transpose to [h][tok][d] ----
__global__ void __launch_bounds__(256, 4)
preround_kernel(const float* __restrict__ Qg, const float* __restrict__ Kg)
{
    const int z = blockIdx.z, h = blockIdx.y;
    const int r = blockIdx.x * 8 + (threadIdx.x >> 5);
    const int c = threadIdx.x & 31;
    const float4* src = (const float4*)(z == 0 ? Qg : Kg);
    uint4* dst = (uint4*)(z == 0 ? Qp : Kp);
    float4 v = src[((size_t)r * HQ + h) * 32 + c];
    uint4 u;
    CVT_RNA(u.x, v.x); CVT_RNA(u.y, v.y); CVT_RNA(u.z, v.z); CVT_RNA(u.w, v.w);
    dst[((size_t)h * QLEN + r) * 32 + c] = u;
}

// ---- kernel 0b: V -> Vhg[h][d][kv] fp16, interleaved within 16-chunks ----
// within each 16-kv chunk, kv pair m (kv {2m,2m+1}) stored at half pos (m&3)*4 + (m>>2)*2
__global__ void __launch_bounds__(256, 4)
vtrans_kernel(const float* __restrict__ Vg)
{
    __shared__ float t[32][33];
    const int h = blockIdx.z;
    const int r0 = blockIdx.x * 32, d0 = blockIdx.y * 32;
    const int x = threadIdx.x & 31, y = threadIdx.x >> 5;
#pragma unroll
    for (int k = 0; k < 4; k++){
        int r = r0 + y + k * 8;
        t[y + k * 8][x] = Vg[((size_t)r * HQ + h) * 128 + d0 + x];
    }
    __syncthreads();
    const int xk = threadIdx.x & 15;          // kv pair index within 32
    const int yy = threadIdx.x >> 4;          // 16 d values
    const int c = xk >> 3, m = xk & 7;
    const int pos = c * 16 + (m & 3) * 4 + (m >> 2) * 2;
#pragma unroll
    for (int k = 0; k < 2; k++){
        int d = d0 + yy + k * 16;
        __half2 hv = __floats2half2_rn(t[2 * xk][yy + k * 16], t[2 * xk + 1][yy + k * 16]);
        *(__half2*)&Vhg[((size_t)h * 128 + d) * KVLEN + r0 + pos] = hv;
    }
}

// =================== QK kernel ===================
#define QK_NT   512
#define PQK     144
#define QK_RED  0
#define QK_Q    2048
#define QK_SLOT (128 * PQK * 4)
#define QK_K0   (2048 + QK_SLOT)
#define QK_TOTAL (QK_K0 + 2 * QK_SLOT)

__device__ __forceinline__ void qk_load_tile(char* base, const float4* g,
                                             size_t rowBase, int tid){
    for (int i = tid; i < 128 * 32; i += QK_NT){
        int r = i >> 5, c = i & 31;
        CPA16(smem_u32(base + r * (PQK * 4) + c * 16), &g[(rowBase + r) * 32 + c]);
    }
}

__global__ void __launch_bounds__(QK_NT, 1)
qk_kernel()
{
    extern __shared__ char sm[];
    const int tid = threadIdx.x, w = tid >> 5, lid = tid & 31;
    const int tq = lid >> 2, tr = lid & 3;
    const int h = blockIdx.y;
    const int qi = (gridDim.x - 1) - blockIdx.x;
    const int q0 = qi * 128;
    const int nt = qi + 1;
    const float scale = 0.08838834764831845f;

    const int wq = w & 3;
    const int wn = w >> 2;

    float* sQ = (float*)(sm + QK_Q);
    const float4* gq = (const float4*)Qp;
    const float4* gk = (const float4*)Kp;

    qk_load_tile(sm + QK_Q, gq, (size_t)h * QLEN + q0, tid);
    qk_load_tile(sm + QK_K0, gk, (size_t)h * KVLEN, tid);
    CPC();

    float rsum[4] = {0.f, 0.f, 0.f, 0.f};
    const size_t tileBase0 = (size_t)(h * 136 + qi * (qi + 1) / 2) * 2048;

    for (int t = 0; t < nt; ++t){
        const int cur = t & 1;

        CPWAIT(0);
        __syncthreads();
        if (t + 1 < nt){
            qk_load_tile(sm + QK_K0 + (cur ^ 1) * QK_SLOT, gk,
                         (size_t)h * KVLEN + (t + 1) * 128, tid);
            CPC();
        }

        float accs[2][4][4];
#pragma unroll
        for (int mf = 0; mf < 2; ++mf)
#pragma unroll
            for (int nf = 0; nf < 4; ++nf)
#pragma unroll
                for (int x = 0; x < 4; ++x) accs[mf][nf][x] = 0.f;

        const float* Kb = (const float*)(sm + QK_K0 + cur * QK_SLOT);
#pragma unroll
        for (int jj = 0; jj < 8; ++jj){
            const int col = jj * 16 + 4 * tr;
            uint4 alo[2], ahi[2], b[4];
#pragma unroll
            for (int mf = 0; mf < 2; ++mf){
                alo[mf] = *(const uint4*)(sQ + (wq*32 + mf*16 + tq) * PQK + col);
                ahi[mf] = *(const uint4*)(sQ + (wq*32 + mf*16 + 8 + tq) * PQK + col);
            }
#pragma unroll
            for (int nf = 0; nf < 4; ++nf)
                b[nf] = *(const uint4*)(Kb + (wn*32 + nf*8 + tq) * PQK + col);
#pragma unroll
            for (int mf = 0; mf < 2; ++mf)
#pragma unroll
                for (int nf = 0; nf < 4; ++nf){
                    MMA_TF32(accs[mf][nf], alo[mf].x, ahi[mf].x, alo[mf].y, ahi[mf].y,
                             b[nf].x, b[nf].y);
                    MMA_TF32(accs[mf][nf], alo[mf].z, ahi[mf].z, alo[mf].w, ahi[mf].w,
                             b[nf].z, b[nf].w);
                }
        }

        // ===== epilogue: exp, rsum, fragment-native coalesced E store =====
        uint4* dstBase = &Ef[tileBase0 + (size_t)t * 2048 + (wq*4 + wn)*128 + lid];
        const bool diag = (t == nt - 1);
        const int k0 = t * 128;
#pragma unroll
        for (int mf = 0; mf < 2; ++mf)
#pragma unroll
            for (int nfp = 0; nfp < 2; ++nfp){
                uint4 u;
                uint32_t* up = (uint32_t*)&u;
#pragma unroll
                for (int sub = 0; sub < 4; ++sub){
                    const int nf = 2*nfp + (sub >> 1);
                    const int hf = sub & 1;
                    const int kvb = k0 + wn*32 + nf*8 + 2*tr;
                    const int qrow = q0 + wq*32 + mf*16 + hf*8 + tq;
                    float e0, e1;
                    if (diag){
                        e0 = (kvb     <= qrow) ? __expf(accs[mf][nf][hf*2    ] * scale) : 0.f;
                        e1 = (kvb + 1 <= qrow) ? __expf(accs[mf][nf][hf*2 + 1] * scale) : 0.f;
                    } else {
                        e0 = __expf(accs[mf][nf][hf*2    ] * scale);
                        e1 = __expf(accs[mf][nf][hf*2 + 1] * scale);
                    }
                    rsum[mf*2 + hf] += e0 + e1;
                    PACK_F16X2(up[sub], e0, e1);
                }
                dstBase[(mf*2 + nfp) * 32] = u;
            }
    }

#pragma unroll
    for (int r = 0; r < 4; ++r){
        rsum[r] += __shfl_xor_sync(0xffffffffu, rsum[r], 1);
        rsum[r] += __shfl_xor_sync(0xffffffffu, rsum[r], 2);
    }
    float* red = (float*)(sm + QK_RED);
    if (tr == 0){
#pragma unroll
        for (int r = 0; r < 4; ++r){
            const int row = wq*32 + (r >> 1)*16 + (r & 1)*8 + tq;
            red[wn * 128 + row] = rsum[r];
        }
    }
    __syncthreads();
    if (tid < 128){
        float s = (red[tid] + red[128 + tid]) + (red[256 + tid] + red[384 + tid]);
        invl_g[h * QLEN + q0 + tid] = 1.0f / s;
    }
}

// =================== PV: O = E(frag-native) * V, fp16 MMA ===================
#define PV_NT   256
#define PVH     144                      // halves pitch
#define PV_VB   (128 * PVH * 2)          // 36864
#define PV_TOTAL (2 * PV_VB)             // 73728

__device__ __forceinline__ void pv_load_v(char* sm, int buf, int k0, int h, int tid){
    char* vb = sm + buf * PV_VB;
    for (int i = tid; i < 128 * 16; i += PV_NT){
        int d = i >> 4, c = i & 15;
        CPA16(smem_u32(vb + d * (PVH * 2) + c * 16),
              &Vhg[((size_t)h * 128 + d) * KVLEN + k0 + c * 8]);
    }
}

__global__ void __launch_bounds__(PV_NT, 2)
pv_kernel(float* __restrict__ Outg)
{
    extern __shared__ char sm[];
    const int tid = threadIdx.x, w = tid >> 5, lid = tid & 31;
    const int tq = lid >> 2, tr = lid & 3;
    const int h = blockIdx.y;
    const int qi = (gridDim.x - 1) - blockIdx.x;
    const int q0 = qi * 128;
    const int nt = qi + 1;                  // 128-kv tiles

    const int wq = w & 3;      // 32-row block
    const int wd = w >> 2;     // 64-d block

    pv_load_v(sm, 0, 0, h, tid);
    CPC();

    float acco[2][8][4];
#pragma unroll
    for (int mf = 0; mf < 2; ++mf)
#pragma unroll
        for (int nf = 0; nf < 8; ++nf)
#pragma unroll
            for (int x = 0; x < 4; ++x) acco[mf][nf][x] = 0.f;

    const size_t tileBase0 = (size_t)(h * 136 + qi * (qi + 1) / 2) * 2048;

    for (int t = 0; t < nt; ++t){
        const int cur = t & 1;
        CPWAIT(0);
        __syncthreads();
        if (t + 1 < nt){ pv_load_v(sm, cur ^ 1, (t + 1) * 128, h, tid); CPC(); }

        const __half* sV = (const __half*)(sm + cur * PV_VB);
        const uint4* eT = &Ef[tileBase0 + (size_t)t * 2048 + wq*4*128 + lid];

#pragma unroll
        for (int wn = 0; wn < 4; ++wn){
            // A fragments: fg = mf*2+cc, u4 = {a0,a1,a2,a3} identity k-perm
            uint4 A[4];
#pragma unroll
            for (int fg = 0; fg < 4; ++fg)
                A[fg] = eT[wn*128 + fg*32];
#pragma unroll
            for (int cc = 0; cc < 2; ++cc){
                const int ch = wn*2 + cc;           // 16-kv chunk
                uint2 b[8];
#pragma unroll
                for (int nf = 0; nf < 8; ++nf)
                    b[nf] = *(const uint2*)(sV + (wd*64 + nf*8 + tq) * PVH + ch*16 + 4*tr);
#pragma unroll
                for (int mf = 0; mf < 2; ++mf){
                    const uint4 a = A[mf*2 + cc];
#pragma unroll
                    for (int nf = 0; nf < 8; ++nf)
                        MMA_F16(acco[mf][nf], a.x, a.y, a.z, a.w, b[nf].x, b[nf].y);
                }
            }
        }
    }

#pragma unroll
    for (int mf = 0; mf < 2; ++mf)
#pragma unroll
        for (int hf = 0; hf < 2; ++hf){
            const int row = wq*32 + mf*16 + hf*8 + tq;
            const float iv = invl_g[h * QLEN + q0 + row];
#pragma unroll
            for (int nf = 0; nf < 8; ++nf){
                const int d = wd*64 + nf*8 + 2*tr;
                *(float2*)&Outg[((size_t)(q0 + row) * HQ + h) * 128 + d] =
                    make_float2(acco[mf][nf][hf*2] * iv, acco[mf][nf][hf*2 + 1] * iv);
            }
        }
}

// =================== colsum over fragment-native E ===================
// block = (tKV, h): owns kv block [tKV*128, +128); sums over all q tiles qi >= tKV
__global__ void __launch_bounds__(256, 4)
roco_colsum_kernel(float* __restrict__ roco, float* __restrict__ roco_sq)
{
    __shared__ float ivs[QLEN];
    __shared__ float redS[8 * 32], redQ[8 * 32];
    const int tKV = blockIdx.x, h = blockIdx.y;
    const int tid = threadIdx.x, w = tid >> 5, lid = tid & 31;
    const int tq = lid >> 2, tr = lid & 3;
    const int wn = w & 3, half = w >> 2;

    for (int i = tid; i < QLEN / 4; i += 256)
        ((float4*)ivs)[i] = ((const float4*)&invl_g[h * QLEN])[i];
    __syncthreads();

    float cs[4][2], cq[4][2];
#pragma unroll
    for (int nf = 0; nf < 4; ++nf){
        cs[nf][0] = cs[nf][1] = 0.f;
        cq[nf][0] = cq[nf][1] = 0.f;
    }

    // chunk list: (qi in tKV..15) x (wq 0..3); split between half 0/1
    const int nqi = 16 - tKV;
    for (int idx = half; idx < nqi * 4; idx += 2){
        const int qi = tKV + (idx >> 2), wq = idx & 3;
        const uint4* cb = &Ef[(size_t)(h * 136 + qi * (qi + 1) / 2 + tKV) * 2048
                             + (wq*4 + wn)*128 + lid];
#pragma unroll
        for (int fg = 0; fg < 4; ++fg){
            uint4 u = cb[fg*32];
            const int mf = fg >> 1, nfp = fg & 1;
            const uint32_t* up = (const uint32_t*)&u;
#pragma unroll
            for (int sub = 0; sub < 4; ++sub){
                const int nf = 2*nfp + (sub >> 1);
                const int hf = sub & 1;
                const int q = qi*128 + wq*32 + mf*16 + hf*8 + tq;
                const float iv = ivs[q];
                float2 f = __half22float2(*(const __half2*)&up[sub]);
                float a = f.x * iv, bb = f.y * iv;
                cs[nf][0] += a;  cs[nf][1] += bb;
                cq[nf][0] = fmaf(a, a, cq[nf][0]);
                cq[nf][1] = fmaf(bb, bb, cq[nf][1]);
            }
        }
    }

    // reduce over tq lanes (lid strides 4,8,16)
#pragma unroll
    for (int nf = 0; nf < 4; ++nf)
#pragma unroll
        for (int p = 0; p < 2; ++p){
#pragma unroll
            for (int off = 4; off < 32; off <<= 1){
                cs[nf][p] += __shfl_xor_sync(0xffffffffu, cs[nf][p], off);
                cq[nf][p] += __shfl_xor_sync(0xffffffffu, cq[nf][p], off);
            }
        }
    if (tq == 0){
#pragma unroll
        for (int nf = 0; nf < 4; ++nf)
#pragma unroll
            for (int p = 0; p < 2; ++p){
                redS[w*32 + tr*8 + nf*2 + p] = cs[nf][p];
                redQ[w*32 + tr*8 + nf*2 + p] = cq[nf][p];
            }
    }
    __syncthreads();
    if (tid < 128){
        const int kv = tid;                 // wn*32 + nf*8 + 2tr + p
        const int kwn = kv >> 5, knf = (kv >> 3) & 3, ktr = (kv & 7) >> 1, kp = kv & 1;
        const int o = ktr*8 + knf*2 + kp;
        float s = redS[kwn*32 + o] + redS[(kwn + 4)*32 + o];
        float qv = redQ[kwn*32 + o] + redQ[(kwn + 4)*32 + o];
        roco[h * QLEN + tKV*128 + kv]    = s;
        roco_sq[h * QLEN + tKV*128 + kv] = qv;
    }
}

extern "C" void kernel_launch(void* const* d_in, const int* in_sizes, int n_in,
                              void* d_out, int out_size)
{
    const float* Qg = (const float*)d_in[0];
    const float* Kg = (const float*)d_in[1];
    const float* Vg = (const float*)d_in[2];
    float* Outg    = (float*)d_out;
    float* roco    = Outg + (size_t)QLEN * HQ * 128;    // 8388608
    float* roco_sq = roco + HQ * QLEN;                  // +65536

    cudaFuncSetAttribute(qk_kernel,
                         cudaFuncAttributeMaxDynamicSharedMemorySize, QK_TOTAL);
    cudaFuncSetAttribute(pv_kernel,
                         cudaFuncAttributeMaxDynamicSharedMemorySize, PV_TOTAL);

    dim3 gpr(QLEN / 8, HQ, 2);
    preround_kernel<<<gpr, 256>>>(Qg, Kg);

    dim3 gvt(KVLEN / 32, 128 / 32, HQ);
    vtrans_kernel<<<gvt, 256>>>(Vg);

    dim3 g1(QLEN / 128, HQ);        // (16, 32)
    qk_kernel<<<g1, QK_NT, QK_TOTAL>>>();

    pv_kernel<<<g1, PV_NT, PV_TOTAL>>>(Outg);

    dim3 g2(16, HQ);                // (tKV, h)
    roco_colsum_kernel<<<g2, 256>>>(roco, roco_sq);
}